// round 3
// baseline (speedup 1.0000x reference)
#include <cuda_runtime.h>
#include <math.h>
#include <stdint.h>

#define BB 16
#define LL 16384
#define CC 256
#define NH 8
#define HD 32
#define TILE 64
#define NTILES (LL / TILE)          // 256
#define SCALE_ATT 0.17677669529663687f  // 1/sqrt(32)
#define LN_EPS 1e-5f

// ---------------- device scratch (no allocation allowed) ----------------
__device__ float g_qproj[BB * CC];              // q after LN + W_q + b_q
__device__ float g_wq[BB * CC * NH];            // [b][k][h] folded q @ W_k
__device__ float g_qb[BB * NH];                 // q_h . b_k
__device__ float g_part[BB * NTILES * NH * CC]; // per-tile  sum p_j * m_j  (33.5 MB)
__device__ float g_md[BB * NTILES * NH * 2];    // per-tile (max, denom)
__device__ float g_attn[BB * CC];               // attention output

// ---------------- K1: q-path prep (16 blocks) ----------------
__global__ void k1_qprep(const float* __restrict__ query,
                         const float* __restrict__ g_q, const float* __restrict__ be_q,
                         const float* __restrict__ W_q, const float* __restrict__ b_q,
                         const float* __restrict__ W_kv, const float* __restrict__ b_kv) {
    int b = blockIdx.x;
    int tid = threadIdx.x;
    __shared__ float qn[CC];
    __shared__ float qp[CC];
    __shared__ float rs[8], rs2[8];

    float v = query[b * CC + tid];
    float s = v, s2 = v * v;
    #pragma unroll
    for (int o = 16; o > 0; o >>= 1) {
        s  += __shfl_xor_sync(~0u, s,  o);
        s2 += __shfl_xor_sync(~0u, s2, o);
    }
    if ((tid & 31) == 0) { rs[tid >> 5] = s; rs2[tid >> 5] = s2; }
    __syncthreads();
    float tot = 0.f, tot2 = 0.f;
    #pragma unroll
    for (int i = 0; i < 8; i++) { tot += rs[i]; tot2 += rs2[i]; }
    float mean = tot * (1.0f / CC);
    float var  = tot2 * (1.0f / CC) - mean * mean;
    float rstd = rsqrtf(var + LN_EPS);
    qn[tid] = (v - mean) * rstd * g_q[tid] + be_q[tid];
    __syncthreads();

    // q = qn @ W_q + b_q
    float acc = b_q[tid];
    for (int k = 0; k < CC; k++) acc += qn[k] * W_q[k * CC + tid];
    qp[tid] = acc;
    g_qproj[b * CC + tid] = acc;
    __syncthreads();

    // wq[k][h] = sum_d qp[h*32+d] * W_kv[k][h*32+d]
    int k = tid;
    #pragma unroll
    for (int h = 0; h < NH; h++) {
        float a = 0.f;
        const float* wrow = W_kv + (size_t)k * (2 * CC) + h * HD;
        const float* qh = qp + h * HD;
        #pragma unroll
        for (int d = 0; d < HD; d++) a += qh[d] * wrow[d];
        g_wq[(b * CC + k) * NH + h] = a;
    }
    if (tid < NH) {
        float a = 0.f;
        const float* qh = qp + tid * HD;
        const float* bk = b_kv + tid * HD;
        #pragma unroll
        for (int d = 0; d < HD; d++) a += qh[d] * bk[d];
        g_qb[b * NH + tid] = a;
    }
}

// ---------------- K2: main fused tile kernel ----------------
// smem layout (floats):
//   mem_s : 64*256      = 16384
//   x_s   : 64*264      = 16896   (m tile, padded)
//   W_s   : 16*260      =  4160
//   wq_s  : 256*8       =  2048
//   gb_s  : 3*256       =   768   (b_ip | g_ip | be_ip)
//   s_s   : 64*8        =   512   (scores -> p)
//   mh_s  : 8
#define SM_MEM   0
#define SM_X     (SM_MEM + 64 * 256)
#define SM_W     (SM_X + 64 * 264)
#define SM_WQ    (SM_W + 16 * 260)
#define SM_GB    (SM_WQ + 2048)
#define SM_S     (SM_GB + 768)
#define SM_MH    (SM_S + 512)
#define SM_TOT   (SM_MH + 16)

extern __shared__ float smem[];

__global__ __launch_bounds__(256, 1)
void k2_main(const float* __restrict__ mem, const float* __restrict__ ior,
             const float* __restrict__ W_ip, const float* __restrict__ b_ip,
             const float* __restrict__ g_ip, const float* __restrict__ be_ip) {
    int b = blockIdx.y, tile = blockIdx.x, tid = threadIdx.x;
    float* mem_s = smem + SM_MEM;
    float* x_s   = smem + SM_X;
    float* W_s   = smem + SM_W;
    float* wq_s  = smem + SM_WQ;
    float* gb_s  = smem + SM_GB;
    float* s_s   = smem + SM_S;
    float* mh_s  = smem + SM_MH;

    const float* memp = mem + ((size_t)b * LL + (size_t)tile * TILE) * CC;
    #pragma unroll
    for (int i = 0; i < 16; i++) {
        int f4 = tid + i * 256;                   // 4096 float4s
        ((float4*)mem_s)[f4] = ((const float4*)memp)[f4];
    }
    const float* wqp = g_wq + (size_t)b * CC * NH;
    #pragma unroll
    for (int i = 0; i < 8; i++) wq_s[tid + i * 256] = wqp[tid + i * 256];
    gb_s[tid]       = b_ip[tid];
    gb_s[256 + tid] = g_ip[tid];
    gb_s[512 + tid] = be_ip[tid];
    __syncthreads();

    // ---- GEMM: X = mem_tile (64x256) @ W_ip (256x256) ----
    int colg = tid & 15;
    int rowg = tid >> 4;
    int col0 = colg * 16;
    int row0 = rowg * 4;
    float acc[4][16];
    #pragma unroll
    for (int i = 0; i < 4; i++)
        #pragma unroll
        for (int j = 0; j < 16; j++) acc[i][j] = 0.f;

    for (int kc = 0; kc < CC; kc += 16) {
        #pragma unroll
        for (int i = 0; i < 4; i++) {
            int f4 = tid + i * 256;               // 1024 float4s = 16x256
            int r  = f4 >> 6;
            int c4 = f4 & 63;
            float4 w = ((const float4*)(W_ip + (size_t)(kc + r) * CC))[c4];
            *(float4*)&W_s[r * 260 + c4 * 4] = w;
        }
        __syncthreads();
        #pragma unroll
        for (int kk = 0; kk < 16; kk++) {
            float a0 = mem_s[(row0 + 0) * 256 + kc + kk];
            float a1 = mem_s[(row0 + 1) * 256 + kc + kk];
            float a2 = mem_s[(row0 + 2) * 256 + kc + kk];
            float a3 = mem_s[(row0 + 3) * 256 + kc + kk];
            const float* wr = &W_s[kk * 260 + col0];
            float4 w0 = *(const float4*)(wr);
            float4 w1 = *(const float4*)(wr + 4);
            float4 w2 = *(const float4*)(wr + 8);
            float4 w3 = *(const float4*)(wr + 12);
            float w[16] = {w0.x, w0.y, w0.z, w0.w, w1.x, w1.y, w1.z, w1.w,
                           w2.x, w2.y, w2.z, w2.w, w3.x, w3.y, w3.z, w3.w};
            #pragma unroll
            for (int j = 0; j < 16; j++) {
                acc[0][j] += a0 * w[j];
                acc[1][j] += a1 * w[j];
                acc[2][j] += a2 * w[j];
                acc[3][j] += a3 * w[j];
            }
        }
        __syncthreads();
    }

    // ---- bias + relu + row LN -> m into x_s ----
    float psum[4] = {0, 0, 0, 0}, psq[4] = {0, 0, 0, 0};
    #pragma unroll
    for (int i = 0; i < 4; i++)
        #pragma unroll
        for (int j = 0; j < 16; j++) {
            float xv = acc[i][j] + gb_s[col0 + j];
            xv = fmaxf(xv, 0.f);
            acc[i][j] = xv;
            psum[i] += xv;
            psq[i]  += xv * xv;
        }
    #pragma unroll
    for (int o = 8; o > 0; o >>= 1)
        #pragma unroll
        for (int i = 0; i < 4; i++) {
            psum[i] += __shfl_xor_sync(~0u, psum[i], o);
            psq[i]  += __shfl_xor_sync(~0u, psq[i],  o);
        }
    #pragma unroll
    for (int i = 0; i < 4; i++) {
        float mean = psum[i] * (1.0f / CC);
        float var  = psq[i] * (1.0f / CC) - mean * mean;
        float rstd = rsqrtf(var + LN_EPS);
        float* xr = &x_s[(row0 + i) * 264 + col0];
        #pragma unroll
        for (int j = 0; j < 16; j++)
            xr[j] = (acc[i][j] - mean) * rstd * gb_s[256 + col0 + j] + gb_s[512 + col0 + j];
    }
    __syncthreads();

    // ---- scores: s[j][h] = (m[j] . wq[:,h] + qb[h]) * scale * ior[b,h,l] ----
    {
        int j  = tid >> 2;
        int h0 = (tid & 3) * 2;
        float d0 = 0.f, d1 = 0.f;
        const float* xr = &x_s[j * 264];
        for (int k = 0; k < CC; k++) {
            float xv = xr[k];
            d0 += xv * wq_s[k * 8 + h0];
            d1 += xv * wq_s[k * 8 + h0 + 1];
        }
        int gl = tile * TILE + j;
        float i0 = ior[((size_t)b * NH + h0) * LL + gl];
        float i1 = ior[((size_t)b * NH + h0 + 1) * LL + gl];
        float qb0 = g_qb[b * NH + h0];
        float qb1 = g_qb[b * NH + h0 + 1];
        s_s[j * 8 + h0]     = (d0 + qb0) * SCALE_ATT * i0;
        s_s[j * 8 + h0 + 1] = (d1 + qb1) * SCALE_ATT * i1;
    }
    __syncthreads();

    // ---- per-head tile max ----
    if (tid < NH) {
        float m = -1e30f;
        for (int j = 0; j < TILE; j++) m = fmaxf(m, s_s[j * 8 + tid]);
        mh_s[tid] = m;
    }
    __syncthreads();
    // ---- p = exp(s - M) ----
    #pragma unroll
    for (int i = 0; i < 2; i++) {
        int idx = tid + i * 256;
        int h = idx & 7;
        s_s[idx] = __expf(s_s[idx] - mh_s[h]);
    }
    __syncthreads();
    // ---- denom + write (M, D) ----
    if (tid < NH) {
        float d = 0.f;
        for (int j = 0; j < TILE; j++) d += s_s[j * 8 + tid];
        float* md = g_md + (size_t)((b * NTILES + tile) * NH + tid) * 2;
        md[0] = mh_s[tid];
        md[1] = d;
    }

    // ---- T accumulation: part[h][c] = sum_j p[j][h] * m[j][c] ----
    {
        int h  = tid >> 5;
        int c0 = (tid & 31) * 8;
        float t[8] = {0, 0, 0, 0, 0, 0, 0, 0};
        for (int jj = 0; jj < TILE; jj++) {
            float w = s_s[jj * 8 + h];
            const float* xr2 = &x_s[jj * 264 + c0];
            float4 v0 = *(const float4*)xr2;
            float4 v1 = *(const float4*)(xr2 + 4);
            t[0] += w * v0.x; t[1] += w * v0.y; t[2] += w * v0.z; t[3] += w * v0.w;
            t[4] += w * v1.x; t[5] += w * v1.y; t[6] += w * v1.z; t[7] += w * v1.w;
        }
        float* pp = g_part + (size_t)((b * NTILES + tile) * NH + h) * CC + c0;
        #pragma unroll
        for (int i = 0; i < 8; i++) pp[i] = t[i];
    }
}

// ---------------- K3: combine tiles + project through W_v ----------------
__global__ void k3_combine(const float* __restrict__ W_kv, const float* __restrict__ b_kv) {
    int b = blockIdx.x >> 3, h = blockIdx.x & 7, tid = threadIdx.x;
    __shared__ float w_s[NTILES];
    __shared__ float tv[CC];
    __shared__ float red[256];
    __shared__ float rsc[8];

    const float* md = g_md + (size_t)((b * NTILES + tid) * NH + h) * 2;
    float Mt = md[0];
    float Dt = md[1];

    // block max over 256 tile maxima
    float m = Mt;
    #pragma unroll
    for (int o = 16; o > 0; o >>= 1) m = fmaxf(m, __shfl_xor_sync(~0u, m, o));
    if ((tid & 31) == 0) rsc[tid >> 5] = m;
    __syncthreads();
    float M = rsc[0];
    #pragma unroll
    for (int i = 1; i < 8; i++) M = fmaxf(M, rsc[i]);

    float sc = __expf(Mt - M);
    w_s[tid] = sc;
    float dp = sc * Dt;
    __syncthreads();          // protect rsc reuse
    #pragma unroll
    for (int o = 16; o > 0; o >>= 1) dp += __shfl_xor_sync(~0u, dp, o);
    if ((tid & 31) == 0) rsc[tid >> 5] = dp;
    __syncthreads();
    float D = 0.f;
    #pragma unroll
    for (int i = 0; i < 8; i++) D += rsc[i];

    // tv[c] = (1/D) * sum_t w_s[t] * part[b][t][h][c]
    float acc = 0.f;
    const float* base = g_part + (size_t)(b * NTILES) * NH * CC + (size_t)h * CC + tid;
    for (int t2 = 0; t2 < NTILES; t2++) acc += w_s[t2] * base[(size_t)t2 * NH * CC];
    tv[tid] = acc / D;
    __syncthreads();

    // out[d] = sum_k tv[k] * W_v[k][h*32+d] + b_v
    int d = tid & 31, g = tid >> 5;
    float a = 0.f;
    for (int k = g * 32; k < g * 32 + 32; k++)
        a += tv[k] * W_kv[(size_t)k * (2 * CC) + CC + h * HD + d];
    red[g * 32 + d] = a;
    __syncthreads();
    if (tid < 32) {
        float s = 0.f;
        #pragma unroll
        for (int gg = 0; gg < 8; gg++) s += red[gg * 32 + tid];
        g_attn[b * CC + h * HD + tid] = s + b_kv[CC + h * HD + tid];
    }
}

// ---------------- K4: residual + LN + FFN (exact GELU) ----------------
__global__ void k4_ffn(const float* __restrict__ query,
                       const float* __restrict__ g_f, const float* __restrict__ be_f,
                       const float* __restrict__ W1, const float* __restrict__ b1,
                       const float* __restrict__ W2, const float* __restrict__ b2,
                       float* __restrict__ out) {
    int b = blockIdx.x, tid = threadIdx.x;
    __shared__ float x_s[CC], hn[CC], h1[512], rs[8], rs2[8];

    float x = g_attn[b * CC + tid] + query[b * CC + tid];
    x_s[tid] = x;
    float s = x, s2 = x * x;
    #pragma unroll
    for (int o = 16; o > 0; o >>= 1) {
        s  += __shfl_xor_sync(~0u, s,  o);
        s2 += __shfl_xor_sync(~0u, s2, o);
    }
    if ((tid & 31) == 0) { rs[tid >> 5] = s; rs2[tid >> 5] = s2; }
    __syncthreads();
    float tot = 0.f, tot2 = 0.f;
    #pragma unroll
    for (int i = 0; i < 8; i++) { tot += rs[i]; tot2 += rs2[i]; }
    float mean = tot * (1.0f / CC);
    float var  = tot2 * (1.0f / CC) - mean * mean;
    float rstd = rsqrtf(var + LN_EPS);
    hn[tid] = (x - mean) * rstd * g_f[tid] + be_f[tid];
    __syncthreads();

    #pragma unroll
    for (int i = 0; i < 2; i++) {
        int f = tid + i * 256;
        float a = b1[f];
        for (int k = 0; k < CC; k++) a += hn[k] * W1[(size_t)k * 512 + f];
        h1[f] = 0.5f * a * (1.0f + erff(a * 0.70710678118654752f));
    }
    __syncthreads();

    float a = b2[tid];
    for (int k = 0; k < 512; k++) a += h1[k] * W2[(size_t)k * CC + tid];
    out[b * CC + tid] = x_s[tid] + a;
}

// ---------------- launch ----------------
extern "C" void kernel_launch(void* const* d_in, const int* in_sizes, int n_in,
                              void* d_out, int out_size) {
    const float* query = (const float*)d_in[0];
    const float* mem   = (const float*)d_in[1];
    const float* ior   = (const float*)d_in[2];
    const float* W_ip  = (const float*)d_in[3];
    const float* b_ip  = (const float*)d_in[4];
    const float* g_ip  = (const float*)d_in[5];
    const float* be_ip = (const float*)d_in[6];
    const float* W_q   = (const float*)d_in[7];
    const float* b_q   = (const float*)d_in[8];
    const float* W_kv  = (const float*)d_in[9];
    const float* b_kv  = (const float*)d_in[10];
    const float* g_q   = (const float*)d_in[11];
    const float* be_q  = (const float*)d_in[12];
    const float* g_f   = (const float*)d_in[13];
    const float* be_f  = (const float*)d_in[14];
    const float* W1    = (const float*)d_in[15];
    const float* b1    = (const float*)d_in[16];
    const float* W2    = (const float*)d_in[17];
    const float* b2    = (const float*)d_in[18];
    float* out = (float*)d_out;

    size_t smem_bytes = (size_t)SM_TOT * sizeof(float);
    cudaFuncSetAttribute(k2_main, cudaFuncAttributeMaxDynamicSharedMemorySize, (int)smem_bytes);

    k1_qprep<<<BB, 256>>>(query, g_q, be_q, W_q, b_q, W_kv, b_kv);
    k2_main<<<dim3(NTILES, BB), 256, smem_bytes>>>(mem, ior, W_ip, b_ip, g_ip, be_ip);
    k3_combine<<<BB * NH, 256>>>(W_kv, b_kv);
    k4_ffn<<<BB, 256>>>(query, g_f, be_f, W1, b1, W2, b2, out);
}

// round 6
// speedup vs baseline: 3.9938x; 3.9938x over previous
#include <cuda_runtime.h>
#include <cuda_bf16.h>
#include <math.h>
#include <stdint.h>

#define BB 16
#define LL 16384
#define CC 256
#define NH 8
#define HD 32
#define TILE 128
#define NTILES (LL / TILE)          // 128
#define SCALE_ATT 0.17677669529663687f
#define LN_EPS 1e-5f

#define PITCH  136                  // bf16 per smem tile row
#define PITCHB 272                  // bytes per smem tile row

// ---------------- device scratch ----------------
__device__ float g_wq[BB * CC * NH];            // gw = g_ip[k] * (q_h . W_k[k,h*32:])
__device__ float g_qb[BB * NH];                 // q_h . b_k
__device__ float g_sg[BB * NH];                 // sum_k gw[k][h]
__device__ float g_bw[BB * NH];                 // sum_k be_ip[k] * wq_raw[k][h]
__device__ float g_part[BB * NTILES * NH * CC]; // per-tile sum (p*rstd) * x
__device__ float g_md[BB * NTILES * NH * 4];    // per-tile (M, D, Q, pad)
__device__ float g_attn[BB * CC];
__device__ __nv_bfloat16 g_b[2][2][CC * 128];   // W_ip^T split: [k-half][hi/lo][n][k]

// ---------------- helpers ----------------
__device__ __forceinline__ uint32_t smem_u32(const void* p) {
    uint32_t a;
    asm("{ .reg .u64 t; cvta.to.shared.u64 t, %1; cvt.u32.u64 %0, t; }" : "=r"(a) : "l"(p));
    return a;
}
__device__ __forceinline__ void ldsm_x4(uint32_t* r, uint32_t a) {
    asm volatile("ldmatrix.sync.aligned.m8n8.x4.shared.b16 {%0,%1,%2,%3}, [%4];"
                 : "=r"(r[0]), "=r"(r[1]), "=r"(r[2]), "=r"(r[3]) : "r"(a));
}
__device__ __forceinline__ void ldsm_x2(uint32_t* r, uint32_t a) {
    asm volatile("ldmatrix.sync.aligned.m8n8.x2.shared.b16 {%0,%1}, [%2];"
                 : "=r"(r[0]), "=r"(r[1]) : "r"(a));
}
__device__ __forceinline__ void mma16816(float* c, const uint32_t* a, const uint32_t* b) {
    asm volatile("mma.sync.aligned.m16n8k16.row.col.f32.bf16.bf16.f32 "
                 "{%0,%1,%2,%3}, {%4,%5,%6,%7}, {%8,%9}, {%0,%1,%2,%3};"
                 : "+f"(c[0]), "+f"(c[1]), "+f"(c[2]), "+f"(c[3])
                 : "r"(a[0]), "r"(a[1]), "r"(a[2]), "r"(a[3]), "r"(b[0]), "r"(b[1]));
}
__device__ __forceinline__ uint32_t pack_bf(__nv_bfloat16 a, __nv_bfloat16 b) {
    return (uint32_t)__bfloat16_as_ushort(a) | ((uint32_t)__bfloat16_as_ushort(b) << 16);
}

// ---------------- K0: split W_ip^T into hi/lo bf16 halves ----------------
__global__ void k0_wprep(const float* __restrict__ W_ip) {
    int idx = blockIdx.x * 256 + threadIdx.x;   // 65536
    int half = idx >> 15;
    int e = idx & 32767;
    int n = e >> 7;          // output channel (B row)
    int c = e & 127;         // k within half
    int k = half * 128 + c;
    float w = W_ip[(size_t)k * CC + n];
    __nv_bfloat16 hi = __float2bfloat16(w);
    __nv_bfloat16 lo = __float2bfloat16(w - __bfloat162float(hi));
    g_b[half][0][n * 128 + c] = hi;
    g_b[half][1][n * 128 + c] = lo;
}

// ---------------- K1: q-path prep ----------------
__global__ void k1_qprep(const float* __restrict__ query,
                         const float* __restrict__ g_q, const float* __restrict__ be_q,
                         const float* __restrict__ W_q, const float* __restrict__ b_q,
                         const float* __restrict__ W_kv, const float* __restrict__ b_kv,
                         const float* __restrict__ g_ip, const float* __restrict__ be_ip) {
    int b = blockIdx.x;
    int tid = threadIdx.x;
    __shared__ float qn[CC], qp[CC], wraw[CC * NH], rs[8], rs2[8];

    float v = query[b * CC + tid];
    float s = v, s2 = v * v;
    #pragma unroll
    for (int o = 16; o > 0; o >>= 1) {
        s  += __shfl_xor_sync(~0u, s,  o);
        s2 += __shfl_xor_sync(~0u, s2, o);
    }
    if ((tid & 31) == 0) { rs[tid >> 5] = s; rs2[tid >> 5] = s2; }
    __syncthreads();
    float tot = 0.f, tot2 = 0.f;
    #pragma unroll
    for (int i = 0; i < 8; i++) { tot += rs[i]; tot2 += rs2[i]; }
    float mean = tot * (1.0f / CC);
    float var  = tot2 * (1.0f / CC) - mean * mean;
    float rstd = rsqrtf(var + LN_EPS);
    qn[tid] = (v - mean) * rstd * g_q[tid] + be_q[tid];
    __syncthreads();

    float acc = b_q[tid];
    for (int k = 0; k < CC; k++) acc += qn[k] * W_q[k * CC + tid];
    qp[tid] = acc;
    __syncthreads();

    int k = tid;
    float gk = g_ip[k];
    #pragma unroll
    for (int h = 0; h < NH; h++) {
        float a = 0.f;
        const float* wrow = W_kv + (size_t)k * (2 * CC) + h * HD;
        const float* qh = qp + h * HD;
        #pragma unroll
        for (int d = 0; d < HD; d++) a += qh[d] * wrow[d];
        wraw[k * NH + h] = a;
        g_wq[(b * CC + k) * NH + h] = gk * a;
    }
    if (tid < NH) {
        float a = 0.f;
        const float* qh = qp + tid * HD;
        const float* bk = b_kv + tid * HD;
        #pragma unroll
        for (int d = 0; d < HD; d++) a += qh[d] * bk[d];
        g_qb[b * NH + tid] = a;
    }
    __syncthreads();
    if (tid < NH) {
        float sg = 0.f, bw = 0.f;
        for (int kk = 0; kk < CC; kk++) {
            float r = wraw[kk * NH + tid];
            sg += g_ip[kk] * r;
            bw += be_ip[kk] * r;
        }
        g_sg[b * NH + tid] = sg;
        g_bw[b * NH + tid] = bw;
    }
}

// ---------------- K2 smem layout (bytes) ----------------
#define SM_A_HI  0u         // 128*272 = 34816
#define SM_A_LO  34816u     // 34816
#define SM_B_HI  69632u     // 256*272 = 69632
#define SM_B_LO  139264u    // 69632  -> end 208896
#define SM_WQ    208896u    // gw 256*8*4 = 8192
#define SM_BIAS  217088u    // 1024
#define SM_TOTAL 218112u
// epilogue overlays (tiles dead by then):
#define SM_XS    0u         // 128*260*4 = 133120
#define SM_SS    133120u    // 128*8*4 = 4096
#define SM_MRS   137216u    // mean[128], rstd[128]
#define SM_MH    138240u    // 8 floats
#define SM_RED   138304u    // 2*128*10*4 = 10240

extern __shared__ char k2smem[];

__global__ __launch_bounds__(256, 1)
void k2_main(const float* __restrict__ mem, const float* __restrict__ ior,
             const float* __restrict__ b_ip) {
    int b = blockIdx.y, tile = blockIdx.x, tid = threadIdx.x;
    int wid = tid >> 5, lane = tid & 31;
    char* sb = k2smem;
    uint32_t sbase = smem_u32(sb);
    float* wq_s = (float*)(sb + SM_WQ);
    float* bias = (float*)(sb + SM_BIAS);
    float* x_s  = (float*)(sb + SM_XS);
    float* s_s  = (float*)(sb + SM_SS);
    float* mrs  = (float*)(sb + SM_MRS);
    float* mh   = (float*)(sb + SM_MH);
    float* red  = (float*)(sb + SM_RED);

    const float* wqp = g_wq + (size_t)b * CC * NH;
    #pragma unroll
    for (int i = 0; i < 8; i++) wq_s[tid + i * 256] = wqp[tid + i * 256];
    bias[tid] = b_ip[tid];

    int wm = wid >> 2, wn = wid & 3;
    int m_base = wm * 64, n_base = wn * 64;

    float acc[4][8][4];
    #pragma unroll
    for (int mt = 0; mt < 4; mt++)
        #pragma unroll
        for (int nt = 0; nt < 8; nt++)
            #pragma unroll
            for (int e = 0; e < 4; e++) acc[mt][nt][e] = 0.f;

    const float* memp = mem + ((size_t)b * LL + (size_t)tile * TILE) * CC;
    int grp = lane >> 3, jj = lane & 7;

    for (int h = 0; h < 2; h++) {
        __syncthreads();    // all prior ldmatrix complete before overwrite
        // ---- A half: fp32 -> bf16 hi/lo ----
        #pragma unroll
        for (int i = 0; i < 16; i++) {
            int f4 = tid + i * 256;           // 4096 = 128 rows * 32 f4
            int row = f4 >> 5;
            int c4  = f4 & 31;
            float4 v = ((const float4*)(memp + (size_t)row * CC + h * 128))[c4];
            __nv_bfloat16 h0 = __float2bfloat16(v.x), h1 = __float2bfloat16(v.y);
            __nv_bfloat16 h2 = __float2bfloat16(v.z), h3 = __float2bfloat16(v.w);
            uint2 uh, ul;
            uh.x = pack_bf(h0, h1); uh.y = pack_bf(h2, h3);
            ul.x = pack_bf(__float2bfloat16(v.x - __bfloat162float(h0)),
                           __float2bfloat16(v.y - __bfloat162float(h1)));
            ul.y = pack_bf(__float2bfloat16(v.z - __bfloat162float(h2)),
                           __float2bfloat16(v.w - __bfloat162float(h3)));
            uint32_t off = (uint32_t)row * PITCHB + (uint32_t)c4 * 8;
            *(uint2*)(sb + SM_A_HI + off) = uh;
            *(uint2*)(sb + SM_A_LO + off) = ul;
        }
        // ---- B half: copy pre-split images (re-pitch 128 -> 136 bf16) ----
        #pragma unroll
        for (int p = 0; p < 2; p++) {
            const uint4* src = (const uint4*)g_b[h][p];
            char* dst = sb + (p ? SM_B_LO : SM_B_HI);
            #pragma unroll
            for (int i = 0; i < 16; i++) {
                int f4 = tid + i * 256;       // 4096 = 256 rows * 16 u4
                int row = f4 >> 4;
                int c16 = f4 & 15;
                *(uint4*)(dst + (uint32_t)row * PITCHB + (uint32_t)c16 * 16) = src[f4];
            }
        }
        __syncthreads();

        #pragma unroll
        for (int k8 = 0; k8 < 8; k8++) {
            int k0 = k8 * 16;
            uint32_t arow = (uint32_t)(m_base + (grp & 1) * 8 + jj) * PITCHB
                          + (uint32_t)(k0 + (grp >> 1) * 8) * 2;
            uint32_t ah[4][4], al[4][4];
            #pragma unroll
            for (int mt = 0; mt < 4; mt++) {
                ldsm_x4(ah[mt], sbase + SM_A_HI + arow + (uint32_t)mt * 16 * PITCHB);
                ldsm_x4(al[mt], sbase + SM_A_LO + arow + (uint32_t)mt * 16 * PITCHB);
            }
            uint32_t brow = (uint32_t)(n_base + jj) * PITCHB
                          + (uint32_t)(k0 + grp * 8) * 2;   // only lanes 0-15 used
            #pragma unroll
            for (int nt = 0; nt < 8; nt++) {
                uint32_t bh[2], bl[2];
                ldsm_x2(bh, sbase + SM_B_HI + brow + (uint32_t)nt * 8 * PITCHB);
                ldsm_x2(bl, sbase + SM_B_LO + brow + (uint32_t)nt * 8 * PITCHB);
                #pragma unroll
                for (int mt = 0; mt < 4; mt++) {
                    mma16816(acc[mt][nt], ah[mt], bh);
                    mma16816(acc[mt][nt], ah[mt], bl);
                    mma16816(acc[mt][nt], al[mt], bh);
                }
            }
        }
    }
    __syncthreads();    // all ldmatrix done; tiles region becomes x_s

    // ---- C -> x_s with bias + relu ----
    #pragma unroll
    for (int mt = 0; mt < 4; mt++) {
        #pragma unroll
        for (int nt = 0; nt < 8; nt++) {
            int m = m_base + mt * 16 + (lane >> 2);
            int n = n_base + nt * 8 + (lane & 3) * 2;
            float b0 = bias[n], b1 = bias[n + 1];
            float2 v01, v23;
            v01.x = fmaxf(acc[mt][nt][0] + b0, 0.f);
            v01.y = fmaxf(acc[mt][nt][1] + b1, 0.f);
            v23.x = fmaxf(acc[mt][nt][2] + b0, 0.f);
            v23.y = fmaxf(acc[mt][nt][3] + b1, 0.f);
            *(float2*)&x_s[m * 260 + n]       = v01;
            *(float2*)&x_s[(m + 8) * 260 + n] = v23;
        }
    }
    __syncthreads();

    // ---- stats + head dots (all 256 threads, half-row each) ----
    {
        int row = tid & 127, half = tid >> 7;
        const float* xr = &x_s[row * 260 + half * 128];
        float sum = 0.f, sq = 0.f;
        float d[8] = {0, 0, 0, 0, 0, 0, 0, 0};
        for (int k = 0; k < 128; k += 4) {
            float4 v = *(const float4*)(xr + k);
            float xv[4] = {v.x, v.y, v.z, v.w};
            sum += v.x + v.y + v.z + v.w;
            sq  += v.x * v.x + v.y * v.y + v.z * v.z + v.w * v.w;
            int kk = half * 128 + k;
            #pragma unroll
            for (int e = 0; e < 4; e++) {
                float4 w0 = *(const float4*)&wq_s[(kk + e) * 8];
                float4 w1 = *(const float4*)&wq_s[(kk + e) * 8 + 4];
                d[0] += xv[e] * w0.x; d[1] += xv[e] * w0.y;
                d[2] += xv[e] * w0.z; d[3] += xv[e] * w0.w;
                d[4] += xv[e] * w1.x; d[5] += xv[e] * w1.y;
                d[6] += xv[e] * w1.z; d[7] += xv[e] * w1.w;
            }
        }
        float* r = &red[(half * 128 + row) * 10];
        r[0] = sum; r[1] = sq;
        #pragma unroll
        for (int hh = 0; hh < 8; hh++) r[2 + hh] = d[hh];
    }
    __syncthreads();

    // ---- finalize LN stats + scores (row per thread) ----
    if (tid < 128) {
        int row = tid;
        const float* r0 = &red[row * 10];
        const float* r1 = &red[(128 + row) * 10];
        float sum = r0[0] + r1[0];
        float sq  = r0[1] + r1[1];
        float mean = sum * (1.0f / CC);
        float var  = sq * (1.0f / CC) - mean * mean;
        float rstd = rsqrtf(var + LN_EPS);
        mrs[row] = mean;
        mrs[128 + row] = rstd;
        int gl = tile * TILE + row;
        #pragma unroll
        for (int h = 0; h < NH; h++) {
            float dh = r0[2 + h] + r1[2 + h];
            float s = (rstd * (dh - mean * g_sg[b * NH + h]) + g_bw[b * NH + h]
                       + g_qb[b * NH + h]) * SCALE_ATT
                      * ior[((size_t)b * NH + h) * LL + gl];
            s_s[row * 8 + h] = s;
        }
    }
    __syncthreads();
    if (tid < NH) {
        float m = -1e30f;
        for (int j = 0; j < TILE; j++) m = fmaxf(m, s_s[j * 8 + tid]);
        mh[tid] = m;
    }
    __syncthreads();
    if (tid < 128) {
        #pragma unroll
        for (int h = 0; h < NH; h++)
            s_s[tid * 8 + h] = __expf(s_s[tid * 8 + h] - mh[h]);
    }
    __syncthreads();
    if (tid < NH) {
        float D = 0.f, Q = 0.f;
        for (int j = 0; j < TILE; j++) {
            float p = s_s[j * 8 + tid];
            D += p;
            Q += p * mrs[128 + j] * mrs[j];
        }
        float* md = &g_md[(size_t)((b * NTILES + tile) * NH + tid) * 4];
        md[0] = mh[tid];
        md[1] = D;
        md[2] = Q;
    }
    // ---- partial sum_j (p*rstd) * x ----
    {
        int h  = tid >> 5;
        int c0 = (tid & 31) * 8;
        float t[8] = {0, 0, 0, 0, 0, 0, 0, 0};
        for (int j = 0; j < TILE; j++) {
            float w = s_s[j * 8 + h] * mrs[128 + j];
            float4 v0 = *(const float4*)&x_s[j * 260 + c0];
            float4 v1 = *(const float4*)&x_s[j * 260 + c0 + 4];
            t[0] += w * v0.x; t[1] += w * v0.y; t[2] += w * v0.z; t[3] += w * v0.w;
            t[4] += w * v1.x; t[5] += w * v1.y; t[6] += w * v1.z; t[7] += w * v1.w;
        }
        float* pp = g_part + (size_t)((b * NTILES + tile) * NH + h) * CC + c0;
        *(float4*)pp       = make_float4(t[0], t[1], t[2], t[3]);
        *(float4*)(pp + 4) = make_float4(t[4], t[5], t[6], t[7]);
    }
}

// ---------------- K3: combine tiles + project through W_v ----------------
__global__ void k3_combine(const float* __restrict__ W_kv, const float* __restrict__ b_kv,
                           const float* __restrict__ g_ip, const float* __restrict__ be_ip) {
    int b = blockIdx.x >> 3, h = blockIdx.x & 7, tid = threadIdx.x;
    __shared__ float w_s[NTILES];
    __shared__ float tv[CC];
    __shared__ float redx[256];
    __shared__ float rsc[8], rsc2[8], rsc3[8];

    float Mt = -1e30f, Dt = 0.f, Qt = 0.f;
    if (tid < NTILES) {
        const float* md = &g_md[(size_t)((b * NTILES + tid) * NH + h) * 4];
        Mt = md[0]; Dt = md[1]; Qt = md[2];
    }

    float m = Mt;
    #pragma unroll
    for (int o = 16; o > 0; o >>= 1) m = fmaxf(m, __shfl_xor_sync(~0u, m, o));
    if ((tid & 31) == 0) rsc[tid >> 5] = m;
    __syncthreads();
    float M = rsc[0];
    #pragma unroll
    for (int i = 1; i < 8; i++) M = fmaxf(M, rsc[i]);

    float sc = __expf(Mt - M);
    if (tid < NTILES) w_s[tid] = sc;
    float dp = sc * Dt, qp = sc * Qt;
    __syncthreads();
    #pragma unroll
    for (int o = 16; o > 0; o >>= 1) {
        dp += __shfl_xor_sync(~0u, dp, o);
        qp += __shfl_xor_sync(~0u, qp, o);
    }
    if ((tid & 31) == 0) { rsc2[tid >> 5] = dp; rsc3[tid >> 5] = qp; }
    __syncthreads();
    float D = 0.f, Q = 0.f;
    #pragma unroll
    for (int i = 0; i < 8; i++) { D += rsc2[i]; Q += rsc3[i]; }

    float acc = 0.f;
    const float* base = g_part + (size_t)(b * NTILES) * NH * CC + (size_t)h * CC + tid;
    for (int t2 = 0; t2 < NTILES; t2++) acc += w_s[t2] * base[(size_t)t2 * NH * CC];
    tv[tid] = g_ip[tid] * (acc - Q) / D + be_ip[tid];
    __syncthreads();

    int d = tid & 31, g = tid >> 5;
    float a = 0.f;
    for (int k = g * 32; k < g * 32 + 32; k++)
        a += tv[k] * W_kv[(size_t)k * (2 * CC) + CC + h * HD + d];
    redx[g * 32 + d] = a;
    __syncthreads();
    if (tid < 32) {
        float s = 0.f;
        #pragma unroll
        for (int gg = 0; gg < 8; gg++) s += redx[gg * 32 + tid];
        g_attn[b * CC + h * HD + tid] = s + b_kv[CC + h * HD + tid];
    }
}

// ---------------- K4: residual + LN + FFN ----------------
__global__ void k4_ffn(const float* __restrict__ query,
                       const float* __restrict__ g_f, const float* __restrict__ be_f,
                       const float* __restrict__ W1, const float* __restrict__ b1,
                       const float* __restrict__ W2, const float* __restrict__ b2,
                       float* __restrict__ out) {
    int b = blockIdx.x, tid = threadIdx.x;
    __shared__ float x_s[CC], hn[CC], h1[512], rs[8], rs2[8];

    float x = g_attn[b * CC + tid] + query[b * CC + tid];
    x_s[tid] = x;
    float s = x, s2 = x * x;
    #pragma unroll
    for (int o = 16; o > 0; o >>= 1) {
        s  += __shfl_xor_sync(~0u, s,  o);
        s2 += __shfl_xor_sync(~0u, s2, o);
    }
    if ((tid & 31) == 0) { rs[tid >> 5] = s; rs2[tid >> 5] = s2; }
    __syncthreads();
    float tot = 0.f, tot2 = 0.f;
    #pragma unroll
    for (int i = 0; i < 8; i++) { tot += rs[i]; tot2 += rs2[i]; }
    float mean = tot * (1.0f / CC);
    float var  = tot2 * (1.0f / CC) - mean * mean;
    float rstd = rsqrtf(var + LN_EPS);
    hn[tid] = (x - mean) * rstd * g_f[tid] + be_f[tid];
    __syncthreads();

    #pragma unroll
    for (int i = 0; i < 2; i++) {
        int f = tid + i * 256;
        float a = b1[f];
        for (int k = 0; k < CC; k++) a += hn[k] * W1[(size_t)k * 512 + f];
        h1[f] = 0.5f * a * (1.0f + erff(a * 0.70710678118654752f));
    }
    __syncthreads();

    float a = b2[tid];
    for (int k = 0; k < 512; k++) a += h1[k] * W2[(size_t)k * CC + tid];
    out[b * CC + tid] = x_s[tid] + a;
}

// ---------------- launch ----------------
extern "C" void kernel_launch(void* const* d_in, const int* in_sizes, int n_in,
                              void* d_out, int out_size) {
    const float* query = (const float*)d_in[0];
    const float* mem   = (const float*)d_in[1];
    const float* ior   = (const float*)d_in[2];
    const float* W_ip  = (const float*)d_in[3];
    const float* b_ip  = (const float*)d_in[4];
    const float* g_ip  = (const float*)d_in[5];
    const float* be_ip = (const float*)d_in[6];
    const float* W_q   = (const float*)d_in[7];
    const float* b_q   = (const float*)d_in[8];
    const float* W_kv  = (const float*)d_in[9];
    const float* b_kv  = (const float*)d_in[10];
    const float* g_q   = (const float*)d_in[11];
    const float* be_q  = (const float*)d_in[12];
    const float* g_f   = (const float*)d_in[13];
    const float* be_f  = (const float*)d_in[14];
    const float* W1    = (const float*)d_in[15];
    const float* b1    = (const float*)d_in[16];
    const float* W2    = (const float*)d_in[17];
    const float* b2    = (const float*)d_in[18];
    float* out = (float*)d_out;

    cudaFuncSetAttribute(k2_main, cudaFuncAttributeMaxDynamicSharedMemorySize,
                         (int)SM_TOTAL);

    k0_wprep<<<256, 256>>>(W_ip);
    k1_qprep<<<BB, 256>>>(query, g_q, be_q, W_q, b_q, W_kv, b_kv, g_ip, be_ip);
    k2_main<<<dim3(NTILES, BB), 256, SM_TOTAL>>>(mem, ior, b_ip);
    k3_combine<<<BB * NH, 256>>>(W_kv, b_kv, g_ip, be_ip);
    k4_ffn<<<BB, 256>>>(query, g_f, be_f, W1, b1, W2, b2, out);
}

// round 9
// speedup vs baseline: 5.3643x; 1.3432x over previous
#include <cuda_runtime.h>
#include <cuda_bf16.h>
#include <math.h>
#include <stdint.h>

#define BB 16
#define LL 16384
#define CC 256
#define NH 8
#define HD 32
#define TILE 128
#define NTILES (LL / TILE)          // 128
#define SCALE_ATT 0.17677669529663687f
#define LN_EPS 1e-5f

#define PITCHB 272u    // bytes per 128-col bf16 row
#define PITCHX 528u    // bytes per 256-col bf16 row

// ---------------- device scratch ----------------
__device__ float g_wq[BB * CC * NH];
__device__ float g_qb[BB * NH];
__device__ float g_sg[BB * NH];
__device__ float g_bw[BB * NH];
__device__ float g_part[BB * NTILES * NH * CC];   // fp32
__device__ float g_md[BB * NTILES * NH * 4];
__device__ float g_attn[BB * CC];
__device__ __nv_bfloat16 g_bimg[2][2][CC * 128];  // W_ip^T split [k-half][hi/lo][n][kc]
__device__ float g_x[BB * CC];
__device__ float g_hn[BB * CC];
__device__ float g_h1[BB * 512];

// ---------------- helpers ----------------
__device__ __forceinline__ uint32_t smem_u32(const void* p) {
    uint32_t a;
    asm("{ .reg .u64 t; cvta.to.shared.u64 t, %1; cvt.u32.u64 %0, t; }" : "=r"(a) : "l"(p));
    return a;
}
__device__ __forceinline__ void ldsm_x4(uint32_t* r, uint32_t a) {
    asm volatile("ldmatrix.sync.aligned.m8n8.x4.shared.b16 {%0,%1,%2,%3}, [%4];"
                 : "=r"(r[0]), "=r"(r[1]), "=r"(r[2]), "=r"(r[3]) : "r"(a));
}
__device__ __forceinline__ void ldsm_x2(uint32_t* r, uint32_t a) {
    asm volatile("ldmatrix.sync.aligned.m8n8.x2.shared.b16 {%0,%1}, [%2];"
                 : "=r"(r[0]), "=r"(r[1]) : "r"(a));
}
__device__ __forceinline__ void mma16816(float* c, const uint32_t* a, const uint32_t* b) {
    asm volatile("mma.sync.aligned.m16n8k16.row.col.f32.bf16.bf16.f32 "
                 "{%0,%1,%2,%3}, {%4,%5,%6,%7}, {%8,%9}, {%0,%1,%2,%3};"
                 : "+f"(c[0]), "+f"(c[1]), "+f"(c[2]), "+f"(c[3])
                 : "r"(a[0]), "r"(a[1]), "r"(a[2]), "r"(a[3]), "r"(b[0]), "r"(b[1]));
}
__device__ __forceinline__ uint32_t pack_bf(float a, float b) {
    return (uint32_t)__bfloat16_as_ushort(__float2bfloat16(a))
         | ((uint32_t)__bfloat16_as_ushort(__float2bfloat16(b)) << 16);
}
__device__ __forceinline__ void cp_async16(uint32_t dst, const void* src) {
    asm volatile("cp.async.cg.shared.global [%0], [%1], 16;" :: "r"(dst), "l"(src));
}
__device__ __forceinline__ void cp_commit() {
    asm volatile("cp.async.commit_group;" ::: "memory");
}
__device__ __forceinline__ void cp_wait0() {
    asm volatile("cp.async.wait_group 0;" ::: "memory");
}

// ---------------- K0: split W_ip^T into hi/lo bf16 half images ----------------
__global__ void k0_wprep(const float* __restrict__ W_ip) {
    int idx = blockIdx.x * 256 + threadIdx.x;
    int half = idx >> 15;
    int e = idx & 32767;
    int n = e >> 7;
    int c = e & 127;
    int k = half * 128 + c;
    float w = W_ip[(size_t)k * CC + n];
    __nv_bfloat16 hi = __float2bfloat16(w);
    __nv_bfloat16 lo = __float2bfloat16(w - __bfloat162float(hi));
    g_bimg[half][0][n * 128 + c] = hi;
    g_bimg[half][1][n * 128 + c] = lo;
}

// ---------------- K1: q-path prep ----------------
__global__ void k1_qprep(const float* __restrict__ query,
                         const float* __restrict__ g_q, const float* __restrict__ be_q,
                         const float* __restrict__ W_q, const float* __restrict__ b_q,
                         const float* __restrict__ W_kv, const float* __restrict__ b_kv,
                         const float* __restrict__ g_ip, const float* __restrict__ be_ip) {
    int b = blockIdx.x;
    int tid = threadIdx.x;
    __shared__ float qn[CC], qp[CC], wraw[CC * NH], rs[8], rs2[8];

    float v = query[b * CC + tid];
    float s = v, s2 = v * v;
    #pragma unroll
    for (int o = 16; o > 0; o >>= 1) {
        s  += __shfl_xor_sync(~0u, s,  o);
        s2 += __shfl_xor_sync(~0u, s2, o);
    }
    if ((tid & 31) == 0) { rs[tid >> 5] = s; rs2[tid >> 5] = s2; }
    __syncthreads();
    float tot = 0.f, tot2 = 0.f;
    #pragma unroll
    for (int i = 0; i < 8; i++) { tot += rs[i]; tot2 += rs2[i]; }
    float mean = tot * (1.0f / CC);
    float var  = tot2 * (1.0f / CC) - mean * mean;
    float rstd = rsqrtf(var + LN_EPS);
    qn[tid] = (v - mean) * rstd * g_q[tid] + be_q[tid];
    __syncthreads();

    float acc = b_q[tid];
    for (int k = 0; k < CC; k++) acc += qn[k] * W_q[k * CC + tid];
    qp[tid] = acc;
    __syncthreads();

    int k = tid;
    float gk = g_ip[k];
    #pragma unroll
    for (int h = 0; h < NH; h++) {
        float a = 0.f;
        const float* wrow = W_kv + (size_t)k * (2 * CC) + h * HD;
        const float* qh = qp + h * HD;
        #pragma unroll
        for (int d = 0; d < HD; d++) a += qh[d] * wrow[d];
        wraw[k * NH + h] = a;
        g_wq[(b * CC + k) * NH + h] = gk * a;
    }
    if (tid < NH) {
        float a = 0.f;
        const float* qh = qp + tid * HD;
        const float* bk = b_kv + tid * HD;
        #pragma unroll
        for (int d = 0; d < HD; d++) a += qh[d] * bk[d];
        g_qb[b * NH + tid] = a;
    }
    __syncthreads();
    if (tid < NH) {
        float sg = 0.f, bw = 0.f;
        for (int kk = 0; kk < CC; kk++) {
            float r = wraw[kk * NH + tid];
            sg += g_ip[kk] * r;
            bw += be_ip[kk] * r;
        }
        g_sg[b * NH + tid] = sg;
        g_bw[b * NH + tid] = bw;
    }
}

// ---------------- K2 smem layout (bytes) ----------------
#define SM_AH    0u
#define SM_AL    34816u
#define SM_BH    69632u
#define SM_BL    139264u
#define SM_BIAS  208896u
#define SM_WQT   209920u     // 8*528 = 4224
#define SM_TOTAL 214144u
// overlays (valid after GEMM):
#define SM_XBF   0u          // 128*528 = 67584
#define SM_XT    69632u      // 256*272 = 69632
#define SM_REDS  139264u     // 4096
#define SM_SS    143360u     // 4096
#define SM_MRS   147456u     // 1024
#define SM_MH    148480u     // 64
#define SM_PT    148544u     // 16*272 = 4352

extern __shared__ char k2smem[];

__global__ __launch_bounds__(256, 1)
void k2_main(const float* __restrict__ mem, const float* __restrict__ ior,
             const float* __restrict__ b_ip) {
    int b = blockIdx.y, tile = blockIdx.x, tid = threadIdx.x;
    int wid = tid >> 5, lane = tid & 31;
    char* sb = k2smem;
    uint32_t sbase = smem_u32(sb);
    float* bias = (float*)(sb + SM_BIAS);
    float* s_s  = (float*)(sb + SM_SS);
    float* mrs  = (float*)(sb + SM_MRS);
    float* mh   = (float*)(sb + SM_MH);
    float* reds = (float*)(sb + SM_REDS);

    // constants: bias + wq^T [h][k] bf16 (k2 prologue, not overlaid)
    bias[tid] = b_ip[tid];
    {
        const float* wp = &g_wq[(size_t)(b * CC + tid) * NH];
        #pragma unroll
        for (int h = 0; h < NH; h++)
            *(__nv_bfloat16*)(sb + SM_WQT + (uint32_t)h * PITCHX + (uint32_t)tid * 2)
                = __float2bfloat16(wp[h]);
    }

    int wm = wid >> 2, wn = wid & 3;
    int m_base = wm * 64, n_base = wn * 64;
    int grp = lane >> 3, jj = lane & 7;

    float acc[4][8][4];
    #pragma unroll
    for (int mt = 0; mt < 4; mt++)
        #pragma unroll
        for (int nt = 0; nt < 8; nt++)
            #pragma unroll
            for (int e = 0; e < 4; e++) acc[mt][nt][e] = 0.f;

    const float* memp = mem + ((size_t)b * LL + (size_t)tile * TILE) * CC;

    for (int h = 0; h < 2; h++) {
        __syncthreads();
        // B halves via cp.async (pre-split hi/lo, re-pitch 256B -> 272B rows)
        #pragma unroll
        for (int p = 0; p < 2; p++) {
            const char* src = (const char*)g_bimg[h][p];
            uint32_t dst = sbase + (p ? SM_BL : SM_BH);
            #pragma unroll
            for (int i = 0; i < 16; i++) {
                int u = tid + i * 256;
                int row = u >> 4, c16 = u & 15;
                cp_async16(dst + (uint32_t)row * PITCHB + (uint32_t)c16 * 16,
                           src + (size_t)row * 256 + c16 * 16);
            }
        }
        cp_commit();
        // A half: fp32 -> bf16 hi/lo
        #pragma unroll
        for (int i = 0; i < 16; i++) {
            int f4 = tid + i * 256;
            int row = f4 >> 5, c4 = f4 & 31;
            float4 v = ((const float4*)(memp + (size_t)row * CC + h * 128))[c4];
            __nv_bfloat16 h0 = __float2bfloat16(v.x), h1 = __float2bfloat16(v.y);
            __nv_bfloat16 h2 = __float2bfloat16(v.z), h3 = __float2bfloat16(v.w);
            uint2 uh, ul;
            uh.x = (uint32_t)__bfloat16_as_ushort(h0)
                 | ((uint32_t)__bfloat16_as_ushort(h1) << 16);
            uh.y = (uint32_t)__bfloat16_as_ushort(h2)
                 | ((uint32_t)__bfloat16_as_ushort(h3) << 16);
            ul.x = pack_bf(v.x - __bfloat162float(h0), v.y - __bfloat162float(h1));
            ul.y = pack_bf(v.z - __bfloat162float(h2), v.w - __bfloat162float(h3));
            uint32_t off = (uint32_t)row * PITCHB + (uint32_t)c4 * 8;
            *(uint2*)(sb + SM_AH + off) = uh;
            *(uint2*)(sb + SM_AL + off) = ul;
        }
        cp_wait0();
        __syncthreads();

        // 3-pass MMA (validated R5 scheme): AhBh + AhBl + AlBh
        #pragma unroll
        for (int k8 = 0; k8 < 8; k8++) {
            int k0 = k8 * 16;
            uint32_t arow = (uint32_t)(m_base + (grp & 1) * 8 + jj) * PITCHB
                          + (uint32_t)(k0 + (grp >> 1) * 8) * 2;
            uint32_t ah[4][4], al[4][4];
            #pragma unroll
            for (int mt = 0; mt < 4; mt++) {
                ldsm_x4(ah[mt], sbase + SM_AH + arow + (uint32_t)mt * 16 * PITCHB);
                ldsm_x4(al[mt], sbase + SM_AL + arow + (uint32_t)mt * 16 * PITCHB);
            }
            uint32_t brow = (uint32_t)(n_base + (grp >> 1) * 8 + jj) * PITCHB
                          + (uint32_t)(k0 + (grp & 1) * 8) * 2;
            #pragma unroll
            for (int np = 0; np < 4; np++) {
                uint32_t bh[4], bl[4];
                ldsm_x4(bh, sbase + SM_BH + brow + (uint32_t)np * 16 * PITCHB);
                ldsm_x4(bl, sbase + SM_BL + brow + (uint32_t)np * 16 * PITCHB);
                #pragma unroll
                for (int mt = 0; mt < 4; mt++) {
                    mma16816(acc[mt][np * 2 + 0], ah[mt], bh + 0);
                    mma16816(acc[mt][np * 2 + 1], ah[mt], bh + 2);
                    mma16816(acc[mt][np * 2 + 0], ah[mt], bl + 0);
                    mma16816(acc[mt][np * 2 + 1], ah[mt], bl + 2);
                    mma16816(acc[mt][np * 2 + 0], al[mt], bh + 0);
                    mma16816(acc[mt][np * 2 + 1], al[mt], bh + 2);
                }
            }
        }
    }
    __syncthreads();

    // E1: bias+relu -> xbf [j][c] + xT [c][j], LN partials
    #pragma unroll
    for (int mt = 0; mt < 4; mt++) {
        int r0 = m_base + mt * 16 + (lane >> 2);
        float s0 = 0.f, q0 = 0.f, s1 = 0.f, q1 = 0.f;
        #pragma unroll
        for (int nt = 0; nt < 8; nt++) {
            int n = n_base + nt * 8 + (lane & 3) * 2;
            float b0 = bias[n], b1 = bias[n + 1];
            float x00 = fmaxf(acc[mt][nt][0] + b0, 0.f);
            float x01 = fmaxf(acc[mt][nt][1] + b1, 0.f);
            float x10 = fmaxf(acc[mt][nt][2] + b0, 0.f);
            float x11 = fmaxf(acc[mt][nt][3] + b1, 0.f);
            s0 += x00 + x01; q0 += x00 * x00 + x01 * x01;
            s1 += x10 + x11; q1 += x10 * x10 + x11 * x11;
            *(uint32_t*)(sb + SM_XBF + (uint32_t)r0 * PITCHX + (uint32_t)n * 2)
                = pack_bf(x00, x01);
            *(uint32_t*)(sb + SM_XBF + (uint32_t)(r0 + 8) * PITCHX + (uint32_t)n * 2)
                = pack_bf(x10, x11);
            *(__nv_bfloat16*)(sb + SM_XT + (uint32_t)n * PITCHB + (uint32_t)r0 * 2)
                = __float2bfloat16(x00);
            *(__nv_bfloat16*)(sb + SM_XT + (uint32_t)(n + 1) * PITCHB + (uint32_t)r0 * 2)
                = __float2bfloat16(x01);
            *(__nv_bfloat16*)(sb + SM_XT + (uint32_t)n * PITCHB + (uint32_t)(r0 + 8) * 2)
                = __float2bfloat16(x10);
            *(__nv_bfloat16*)(sb + SM_XT + (uint32_t)(n + 1) * PITCHB + (uint32_t)(r0 + 8) * 2)
                = __float2bfloat16(x11);
        }
        #pragma unroll
        for (int o = 1; o <= 2; o <<= 1) {
            s0 += __shfl_xor_sync(~0u, s0, o); q0 += __shfl_xor_sync(~0u, q0, o);
            s1 += __shfl_xor_sync(~0u, s1, o); q1 += __shfl_xor_sync(~0u, q1, o);
        }
        if ((lane & 3) == 0) {
            reds[(wn * 128 + r0) * 2]         = s0;
            reds[(wn * 128 + r0) * 2 + 1]     = q0;
            reds[(wn * 128 + r0 + 8) * 2]     = s1;
            reds[(wn * 128 + r0 + 8) * 2 + 1] = q1;
        }
    }
    __syncthreads();

    // E2: finalize LN stats
    if (tid < 128) {
        float s = reds[tid * 2] + reds[(128 + tid) * 2]
                + reds[(256 + tid) * 2] + reds[(384 + tid) * 2];
        float q = reds[tid * 2 + 1] + reds[(128 + tid) * 2 + 1]
                + reds[(256 + tid) * 2 + 1] + reds[(384 + tid) * 2 + 1];
        float mean = s * (1.0f / CC);
        float var  = q * (1.0f / CC) - mean * mean;
        mrs[tid] = mean;
        mrs[128 + tid] = rsqrtf(var + LN_EPS);
    }
    __syncthreads();

    // E3: score dots via MMA; B = wq^T [h][k] non-trans x2 (validated pattern)
    {
        float cd[4] = {0.f, 0.f, 0.f, 0.f};
        #pragma unroll
        for (int k8 = 0; k8 < 16; k8++) {
            uint32_t a[4];
            ldsm_x4(a, sbase + SM_XBF
                       + (uint32_t)(wid * 16 + (grp & 1) * 8 + jj) * PITCHX
                       + (uint32_t)(k8 * 16 + (grp >> 1) * 8) * 2);
            uint32_t bb[2];
            ldsm_x2(bb, sbase + SM_WQT + (uint32_t)(lane & 7) * PITCHX
                       + (uint32_t)(k8 * 16 + ((lane >> 3) & 1) * 8) * 2);
            mma16816(cd, a, bb);
        }
        int r = wid * 16 + (lane >> 2);
        int h0 = (lane & 3) * 2;
        int glb = tile * TILE;
        #pragma unroll
        for (int e = 0; e < 4; e++) {
            int row = r + (e >> 1) * 8;
            int h = h0 + (e & 1);
            float mean = mrs[row], rstd = mrs[128 + row];
            float sv = (rstd * (cd[e] - mean * g_sg[b * NH + h])
                        + g_bw[b * NH + h] + g_qb[b * NH + h]) * SCALE_ATT
                       * ior[((size_t)b * NH + h) * LL + glb + row];
            s_s[row * 8 + h] = sv;
        }
    }
    __syncthreads();

    // E4: softmax partials
    if (tid < NH) {
        float m = -1e30f;
        for (int j = 0; j < TILE; j++) m = fmaxf(m, s_s[j * 8 + tid]);
        mh[tid] = m;
    }
    __syncthreads();
    if (tid < 128) {
        #pragma unroll
        for (int h = 0; h < NH; h++)
            s_s[tid * 8 + h] = __expf(s_s[tid * 8 + h] - mh[h]);
    }
    __syncthreads();
    if (tid < NH) {
        float D = 0.f, Q = 0.f;
        for (int j = 0; j < TILE; j++) {
            float p = s_s[j * 8 + tid];
            D += p;
            Q += p * mrs[128 + j] * mrs[j];
        }
        float* md = &g_md[(size_t)((b * NTILES + tile) * NH + tid) * 4];
        md[0] = mh[tid];
        md[1] = D;
        md[2] = Q;
    }

    // E5: pT bf16 [h][j] (rstd folded), zero rows 8-15
    if (tid < 128) {
        float rstd = mrs[128 + tid];
        #pragma unroll
        for (int h = 0; h < NH; h++)
            *(__nv_bfloat16*)(sb + SM_PT + (uint32_t)h * PITCHB + (uint32_t)tid * 2)
                = __float2bfloat16(s_s[tid * 8 + h] * rstd);
    }
    for (int i = tid; i < 1088; i += 256)
        *(unsigned short*)(sb + SM_PT + 8 * PITCHB + (uint32_t)i * 2) = 0;
    __syncthreads();

    // E6: T = pT @ x via MMA; B = xT [c][j] non-trans x4 (validated pattern)
    {
        float ct[4][4];
        #pragma unroll
        for (int q = 0; q < 4; q++)
            #pragma unroll
            for (int e = 0; e < 4; e++) ct[q][e] = 0.f;
        #pragma unroll
        for (int k8 = 0; k8 < 8; k8++) {
            int j0 = k8 * 16;
            uint32_t a[4];
            ldsm_x4(a, sbase + SM_PT + (uint32_t)((grp & 1) * 8 + jj) * PITCHB
                       + (uint32_t)(j0 + (grp >> 1) * 8) * 2);
            #pragma unroll
            for (int np = 0; np < 2; np++) {
                uint32_t bb[4];
                ldsm_x4(bb, sbase + SM_XT
                           + (uint32_t)(wid * 32 + np * 16 + (grp >> 1) * 8 + jj) * PITCHB
                           + (uint32_t)(j0 + (grp & 1) * 8) * 2);
                mma16816(ct[np * 2 + 0], a, bb + 0);
                mma16816(ct[np * 2 + 1], a, bb + 2);
            }
        }
        int h = lane >> 2;
        float* gp = g_part + (size_t)((b * NTILES + tile) * NH + h) * CC;
        #pragma unroll
        for (int q = 0; q < 4; q++) {
            int c = wid * 32 + (q >> 1) * 16 + (q & 1) * 8 + (lane & 3) * 2;
            gp[c]     = ct[q][0];
            gp[c + 1] = ct[q][1];
        }
    }
}

// ---------------- K3: combine tiles + project through W_v ----------------
__global__ void k3_combine(const float* __restrict__ W_kv, const float* __restrict__ b_kv,
                           const float* __restrict__ g_ip, const float* __restrict__ be_ip) {
    int b = blockIdx.x >> 3, h = blockIdx.x & 7, tid = threadIdx.x;
    __shared__ float w_s[NTILES];
    __shared__ float tv[CC];
    __shared__ float redx[256];
    __shared__ float rsc[8], rsc2[8], rsc3[8];

    float Mt = -1e30f, Dt = 0.f, Qt = 0.f;
    if (tid < NTILES) {
        const float* md = &g_md[(size_t)((b * NTILES + tid) * NH + h) * 4];
        Mt = md[0]; Dt = md[1]; Qt = md[2];
    }

    float m = Mt;
    #pragma unroll
    for (int o = 16; o > 0; o >>= 1) m = fmaxf(m, __shfl_xor_sync(~0u, m, o));
    if ((tid & 31) == 0) rsc[tid >> 5] = m;
    __syncthreads();
    float M = rsc[0];
    #pragma unroll
    for (int i = 1; i < 8; i++) M = fmaxf(M, rsc[i]);

    float sc = __expf(Mt - M);
    if (tid < NTILES) w_s[tid] = sc;
    float dp = sc * Dt, qp = sc * Qt;
    __syncthreads();
    #pragma unroll
    for (int o = 16; o > 0; o >>= 1) {
        dp += __shfl_xor_sync(~0u, dp, o);
        qp += __shfl_xor_sync(~0u, qp, o);
    }
    if ((tid & 31) == 0) { rsc2[tid >> 5] = dp; rsc3[tid >> 5] = qp; }
    __syncthreads();
    float D = 0.f, Q = 0.f;
    #pragma unroll
    for (int i = 0; i < 8; i++) { D += rsc2[i]; Q += rsc3[i]; }

    float acc = 0.f;
    const float* base = g_part + (size_t)(b * NTILES) * NH * CC + (size_t)h * CC + tid;
    for (int t2 = 0; t2 < NTILES; t2++) acc += w_s[t2] * base[(size_t)t2 * NH * CC];
    tv[tid] = g_ip[tid] * (acc - Q) / D + be_ip[tid];
    __syncthreads();

    int d = tid & 31, g = tid >> 5;
    float a = 0.f;
    for (int k = g * 32; k < g * 32 + 32; k++)
        a += tv[k] * W_kv[(size_t)k * (2 * CC) + CC + h * HD + d];
    redx[g * 32 + d] = a;
    __syncthreads();
    if (tid < 32) {
        float s = 0.f;
        #pragma unroll
        for (int gg = 0; gg < 8; gg++) s += redx[gg * 32 + tid];
        g_attn[b * CC + h * HD + tid] = s + b_kv[CC + h * HD + tid];
    }
}

// ---------------- K4a/b/c ----------------
__global__ void k4a_ln(const float* __restrict__ query,
                       const float* __restrict__ g_f, const float* __restrict__ be_f) {
    int b = blockIdx.x, tid = threadIdx.x;
    __shared__ float rs[8], rs2[8];
    float x = g_attn[b * CC + tid] + query[b * CC + tid];
    g_x[b * CC + tid] = x;
    float s = x, s2 = x * x;
    #pragma unroll
    for (int o = 16; o > 0; o >>= 1) {
        s  += __shfl_xor_sync(~0u, s,  o);
        s2 += __shfl_xor_sync(~0u, s2, o);
    }
    if ((tid & 31) == 0) { rs[tid >> 5] = s; rs2[tid >> 5] = s2; }
    __syncthreads();
    float tot = 0.f, tot2 = 0.f;
    #pragma unroll
    for (int i = 0; i < 8; i++) { tot += rs[i]; tot2 += rs2[i]; }
    float mean = tot * (1.0f / CC);
    float var  = tot2 * (1.0f / CC) - mean * mean;
    float rstd = rsqrtf(var + LN_EPS);
    g_hn[b * CC + tid] = (x - mean) * rstd * g_f[tid] + be_f[tid];
}

__global__ void k4b_ffn1(const float* __restrict__ W1, const float* __restrict__ b1) {
    int b = blockIdx.y, tid = threadIdx.x;
    int f = blockIdx.x * 64 + (tid & 63);
    int ks = tid >> 6;
    __shared__ float red[256];
    const float* hn = &g_hn[b * CC];
    float acc = 0.f;
    for (int k = ks * 64; k < ks * 64 + 64; k++)
        acc += hn[k] * W1[(size_t)k * 512 + f];
    red[tid] = acc;
    __syncthreads();
    if (tid < 64) {
        float a = red[tid] + red[64 + tid] + red[128 + tid] + red[192 + tid] + b1[f];
        g_h1[b * 512 + f] = 0.5f * a * (1.0f + erff(a * 0.70710678118654752f));
    }
}

__global__ void k4c_ffn2(const float* __restrict__ W2, const float* __restrict__ b2,
                         float* __restrict__ out) {
    int b = blockIdx.y, tid = threadIdx.x;
    int c = blockIdx.x * 64 + (tid & 63);
    int ks = tid >> 6;
    __shared__ float red[256];
    const float* h1 = &g_h1[b * 512];
    float acc = 0.f;
    for (int k = ks * 128; k < ks * 128 + 128; k++)
        acc += h1[k] * W2[(size_t)k * CC + c];
    red[tid] = acc;
    __syncthreads();
    if (tid < 64) {
        float a = red[tid] + red[64 + tid] + red[128 + tid] + red[192 + tid];
        out[b * CC + c] = g_x[b * CC + c] + a + b2[c];
    }
}

// ---------------- launch ----------------
extern "C" void kernel_launch(void* const* d_in, const int* in_sizes, int n_in,
                              void* d_out, int out_size) {
    const float* query = (const float*)d_in[0];
    const float* mem   = (const float*)d_in[1];
    const float* ior   = (const float*)d_in[2];
    const float* W_ip  = (const float*)d_in[3];
    const float* b_ip  = (const float*)d_in[4];
    const float* g_ipp = (const float*)d_in[5];
    const float* be_ip = (const float*)d_in[6];
    const float* W_q   = (const float*)d_in[7];
    const float* b_q   = (const float*)d_in[8];
    const float* W_kv  = (const float*)d_in[9];
    const float* b_kv  = (const float*)d_in[10];
    const float* g_q   = (const float*)d_in[11];
    const float* be_q  = (const float*)d_in[12];
    const float* g_f   = (const float*)d_in[13];
    const float* be_f  = (const float*)d_in[14];
    const float* W1    = (const float*)d_in[15];
    const float* b1    = (const float*)d_in[16];
    const float* W2    = (const float*)d_in[17];
    const float* b2    = (const float*)d_in[18];
    float* out = (float*)d_out;

    cudaFuncSetAttribute(k2_main, cudaFuncAttributeMaxDynamicSharedMemorySize,
                         (int)SM_TOTAL);

    k0_wprep<<<256, 256>>>(W_ip);
    k1_qprep<<<BB, 256>>>(query, g_q, be_q, W_q, b_q, W_kv, b_kv, g_ipp, be_ip);
    k2_main<<<dim3(NTILES, BB), 256, SM_TOTAL>>>(mem, ior, b_ip);
    k3_combine<<<BB * NH, 256>>>(W_kv, b_kv, g_ipp, be_ip);
    k4a_ln<<<BB, 256>>>(query, g_f, be_f);
    k4b_ffn1<<<dim3(8, BB), 256>>>(W1, b1);
    k4c_ffn2<<<dim3(4, BB), 256>>>(W2, b2, out);
}

// round 10
// speedup vs baseline: 8.0797x; 1.5062x over previous
#include <cuda_runtime.h>
#include <cuda_bf16.h>
#include <math.h>
#include <stdint.h>

#define BB 16
#define LL 16384
#define CC 256
#define NH 8
#define HD 32
#define TILE 128
#define NTILES (LL / TILE)          // 128
#define SCALE_ATT 0.17677669529663687f
#define LN_EPS 1e-5f

#define PITCHB 272u    // bytes per 128-col bf16 row
#define PITCHX 528u    // bytes per 256-col bf16 row

// ---------------- device scratch ----------------
__device__ float g_wq[BB * CC * NH];
__device__ float g_qb[BB * NH];
__device__ float g_sg[BB * NH];
__device__ float g_bw[BB * NH];
__device__ float g_part[BB * NTILES * NH * CC];   // fp32
__device__ float g_md[BB * NTILES * NH * 4];
__device__ float g_attn[BB * CC];
__device__ __nv_bfloat16 g_bflat[CC * CC];        // W_ip^T bf16 [n][k]
__device__ float g_x[BB * CC];
__device__ float g_hn[BB * CC];
__device__ float g_h1[BB * 512];

// ---------------- helpers ----------------
__device__ __forceinline__ uint32_t smem_u32(const void* p) {
    uint32_t a;
    asm("{ .reg .u64 t; cvta.to.shared.u64 t, %1; cvt.u32.u64 %0, t; }" : "=r"(a) : "l"(p));
    return a;
}
__device__ __forceinline__ void ldsm_x4(uint32_t* r, uint32_t a) {
    asm volatile("ldmatrix.sync.aligned.m8n8.x4.shared.b16 {%0,%1,%2,%3}, [%4];"
                 : "=r"(r[0]), "=r"(r[1]), "=r"(r[2]), "=r"(r[3]) : "r"(a));
}
__device__ __forceinline__ void ldsm_x2(uint32_t* r, uint32_t a) {
    asm volatile("ldmatrix.sync.aligned.m8n8.x2.shared.b16 {%0,%1}, [%2];"
                 : "=r"(r[0]), "=r"(r[1]) : "r"(a));
}
__device__ __forceinline__ void mma16816(float* c, const uint32_t* a, const uint32_t* b) {
    asm volatile("mma.sync.aligned.m16n8k16.row.col.f32.bf16.bf16.f32 "
                 "{%0,%1,%2,%3}, {%4,%5,%6,%7}, {%8,%9}, {%0,%1,%2,%3};"
                 : "+f"(c[0]), "+f"(c[1]), "+f"(c[2]), "+f"(c[3])
                 : "r"(a[0]), "r"(a[1]), "r"(a[2]), "r"(a[3]), "r"(b[0]), "r"(b[1]));
}
__device__ __forceinline__ uint32_t pack_bf(float a, float b) {
    return (uint32_t)__bfloat16_as_ushort(__float2bfloat16(a))
         | ((uint32_t)__bfloat16_as_ushort(__float2bfloat16(b)) << 16);
}
__device__ __forceinline__ void cp_async16(uint32_t dst, const void* src) {
    asm volatile("cp.async.cg.shared.global [%0], [%1], 16;" :: "r"(dst), "l"(src));
}
__device__ __forceinline__ void cp_commit() {
    asm volatile("cp.async.commit_group;" ::: "memory");
}
__device__ __forceinline__ void cp_wait0() {
    asm volatile("cp.async.wait_group 0;" ::: "memory");
}

// ---------------- K0: W_ip^T -> bf16 [n][k] (coalesced read, scattered write) ----
__global__ void k0_wprep(const float* __restrict__ W_ip) {
    int k = blockIdx.x;          // 256 blocks
    int n = threadIdx.x;         // 256 threads
    g_bflat[(size_t)n * CC + k] = __float2bfloat16(W_ip[(size_t)k * CC + n]);
}

// ---------------- K1: q-path prep ----------------
__global__ void k1_qprep(const float* __restrict__ query,
                         const float* __restrict__ g_q, const float* __restrict__ be_q,
                         const float* __restrict__ W_q, const float* __restrict__ b_q,
                         const float* __restrict__ W_kv, const float* __restrict__ b_kv,
                         const float* __restrict__ g_ip, const float* __restrict__ be_ip) {
    int b = blockIdx.x;
    int tid = threadIdx.x;
    __shared__ float qn[CC], qp[CC], wraw[CC * NH], rs[8], rs2[8];

    float v = query[b * CC + tid];
    float s = v, s2 = v * v;
    #pragma unroll
    for (int o = 16; o > 0; o >>= 1) {
        s  += __shfl_xor_sync(~0u, s,  o);
        s2 += __shfl_xor_sync(~0u, s2, o);
    }
    if ((tid & 31) == 0) { rs[tid >> 5] = s; rs2[tid >> 5] = s2; }
    __syncthreads();
    float tot = 0.f, tot2 = 0.f;
    #pragma unroll
    for (int i = 0; i < 8; i++) { tot += rs[i]; tot2 += rs2[i]; }
    float mean = tot * (1.0f / CC);
    float var  = tot2 * (1.0f / CC) - mean * mean;
    float rstd = rsqrtf(var + LN_EPS);
    qn[tid] = (v - mean) * rstd * g_q[tid] + be_q[tid];
    __syncthreads();

    float acc = b_q[tid];
    for (int k = 0; k < CC; k++) acc += qn[k] * W_q[k * CC + tid];
    qp[tid] = acc;
    __syncthreads();

    int k = tid;
    float gk = g_ip[k];
    #pragma unroll
    for (int h = 0; h < NH; h++) {
        float a = 0.f;
        const float* wrow = W_kv + (size_t)k * (2 * CC) + h * HD;
        const float* qh = qp + h * HD;
        #pragma unroll
        for (int d = 0; d < HD; d++) a += qh[d] * wrow[d];
        wraw[k * NH + h] = a;
        g_wq[(b * CC + k) * NH + h] = gk * a;
    }
    if (tid < NH) {
        float a = 0.f;
        const float* qh = qp + tid * HD;
        const float* bk = b_kv + tid * HD;
        #pragma unroll
        for (int d = 0; d < HD; d++) a += qh[d] * bk[d];
        g_qb[b * NH + tid] = a;
    }
    __syncthreads();
    if (tid < NH) {
        float sg = 0.f, bw = 0.f;
        for (int kk = 0; kk < CC; kk++) {
            float r = wraw[kk * NH + tid];
            sg += g_ip[kk] * r;
            bw += be_ip[kk] * r;
        }
        g_sg[b * NH + tid] = sg;
        g_bw[b * NH + tid] = bw;
    }
}

// ---------------- K2 smem layout (bytes) ----------------
#define SM_A     0u          // 128*528 = 67584  (A bf16, later XBF)
#define SM_B     67584u      // 256*528 = 135168 -> 202752 (later XT + overlays)
#define SM_BIAS  202752u     // 1024
#define SM_WQT   203776u     // 8*528 = 4224 -> 208000
#define SM_TOTAL 208000u
// overlays (valid after GEMM; A/B dead):
#define SM_XBF   0u          // 128*528 = 67584
#define SM_XT    67584u      // 256*272 = 69632 -> 137216
#define SM_REDS  137216u     // 4096
#define SM_SS    141312u     // 4096
#define SM_MRS   145408u     // 1024
#define SM_MH    146432u     // 64
#define SM_PT    146496u     // 16*272 = 4352 -> 150848

extern __shared__ char k2smem[];

__global__ __launch_bounds__(256, 1)
void k2_main(const float* __restrict__ mem, const float* __restrict__ ior,
             const float* __restrict__ b_ip) {
    int b = blockIdx.y, tile = blockIdx.x, tid = threadIdx.x;
    int wid = tid >> 5, lane = tid & 31;
    char* sb = k2smem;
    uint32_t sbase = smem_u32(sb);
    float* bias = (float*)(sb + SM_BIAS);
    float* s_s  = (float*)(sb + SM_SS);
    float* mrs  = (float*)(sb + SM_MRS);
    float* mh   = (float*)(sb + SM_MH);
    float* reds = (float*)(sb + SM_REDS);

    // ---- B via cp.async (pre-transposed bf16 [n][k], re-pitch 512B -> 528B) ----
    #pragma unroll
    for (int i = 0; i < 32; i++) {
        int u = tid + i * 256;                // 8192 = 256 rows * 32 units
        int row = u >> 5, c16 = u & 31;
        cp_async16(sbase + SM_B + (uint32_t)row * PITCHX + (uint32_t)c16 * 16,
                   (const char*)g_bflat + (size_t)row * 512 + c16 * 16);
    }
    cp_commit();

    // ---- constants: bias + wq^T [h][k] bf16 ----
    bias[tid] = b_ip[tid];
    {
        const float* wp = &g_wq[(size_t)(b * CC + tid) * NH];
        #pragma unroll
        for (int h = 0; h < NH; h++)
            *(__nv_bfloat16*)(sb + SM_WQT + (uint32_t)h * PITCHX + (uint32_t)tid * 2)
                = __float2bfloat16(wp[h]);
    }

    // ---- A: fp32 -> bf16 (single image, full K=256) ----
    const float* memp = mem + ((size_t)b * LL + (size_t)tile * TILE) * CC;
    #pragma unroll
    for (int i = 0; i < 32; i++) {
        int f4 = tid + i * 256;               // 8192 = 128 rows * 64 f4
        int row = f4 >> 6, c4 = f4 & 63;
        float4 v = ((const float4*)(memp + (size_t)row * CC))[c4];
        uint2 u;
        u.x = pack_bf(v.x, v.y); u.y = pack_bf(v.z, v.w);
        *(uint2*)(sb + SM_A + (uint32_t)row * PITCHX + (uint32_t)c4 * 8) = u;
    }
    cp_wait0();
    __syncthreads();

    // ---- main MMA: x = A(128x256) @ B^T, single-pass bf16 ----
    int wm = wid >> 2, wn = wid & 3;
    int m_base = wm * 64, n_base = wn * 64;
    int grp = lane >> 3, jj = lane & 7;

    float acc[4][8][4];
    #pragma unroll
    for (int mt = 0; mt < 4; mt++)
        #pragma unroll
        for (int nt = 0; nt < 8; nt++)
            #pragma unroll
            for (int e = 0; e < 4; e++) acc[mt][nt][e] = 0.f;

    #pragma unroll
    for (int k8 = 0; k8 < 16; k8++) {
        int k0 = k8 * 16;
        uint32_t arow = (uint32_t)(m_base + (grp & 1) * 8 + jj) * PITCHX
                      + (uint32_t)(k0 + (grp >> 1) * 8) * 2;
        uint32_t a[4][4];
        #pragma unroll
        for (int mt = 0; mt < 4; mt++)
            ldsm_x4(a[mt], sbase + SM_A + arow + (uint32_t)mt * 16 * PITCHX);
        uint32_t brow = (uint32_t)(n_base + (grp >> 1) * 8 + jj) * PITCHX
                      + (uint32_t)(k0 + (grp & 1) * 8) * 2;
        #pragma unroll
        for (int np = 0; np < 4; np++) {
            uint32_t bb[4];
            ldsm_x4(bb, sbase + SM_B + brow + (uint32_t)np * 16 * PITCHX);
            #pragma unroll
            for (int mt = 0; mt < 4; mt++) {
                mma16816(acc[mt][np * 2 + 0], a[mt], bb + 0);
                mma16816(acc[mt][np * 2 + 1], a[mt], bb + 2);
            }
        }
    }
    __syncthreads();    // A/B dead; overlays live

    // ---- E1: bias+relu -> xbf [j][c] + xT [c][j], LN partials ----
    #pragma unroll
    for (int mt = 0; mt < 4; mt++) {
        int r0 = m_base + mt * 16 + (lane >> 2);
        float s0 = 0.f, q0 = 0.f, s1 = 0.f, q1 = 0.f;
        #pragma unroll
        for (int nt = 0; nt < 8; nt++) {
            int n = n_base + nt * 8 + (lane & 3) * 2;
            float b0 = bias[n], b1 = bias[n + 1];
            float x00 = fmaxf(acc[mt][nt][0] + b0, 0.f);
            float x01 = fmaxf(acc[mt][nt][1] + b1, 0.f);
            float x10 = fmaxf(acc[mt][nt][2] + b0, 0.f);
            float x11 = fmaxf(acc[mt][nt][3] + b1, 0.f);
            s0 += x00 + x01; q0 += x00 * x00 + x01 * x01;
            s1 += x10 + x11; q1 += x10 * x10 + x11 * x11;
            *(uint32_t*)(sb + SM_XBF + (uint32_t)r0 * PITCHX + (uint32_t)n * 2)
                = pack_bf(x00, x01);
            *(uint32_t*)(sb + SM_XBF + (uint32_t)(r0 + 8) * PITCHX + (uint32_t)n * 2)
                = pack_bf(x10, x11);
            *(__nv_bfloat16*)(sb + SM_XT + (uint32_t)n * PITCHB + (uint32_t)r0 * 2)
                = __float2bfloat16(x00);
            *(__nv_bfloat16*)(sb + SM_XT + (uint32_t)(n + 1) * PITCHB + (uint32_t)r0 * 2)
                = __float2bfloat16(x01);
            *(__nv_bfloat16*)(sb + SM_XT + (uint32_t)n * PITCHB + (uint32_t)(r0 + 8) * 2)
                = __float2bfloat16(x10);
            *(__nv_bfloat16*)(sb + SM_XT + (uint32_t)(n + 1) * PITCHB + (uint32_t)(r0 + 8) * 2)
                = __float2bfloat16(x11);
        }
        #pragma unroll
        for (int o = 1; o <= 2; o <<= 1) {
            s0 += __shfl_xor_sync(~0u, s0, o); q0 += __shfl_xor_sync(~0u, q0, o);
            s1 += __shfl_xor_sync(~0u, s1, o); q1 += __shfl_xor_sync(~0u, q1, o);
        }
        if ((lane & 3) == 0) {
            reds[(wn * 128 + r0) * 2]         = s0;
            reds[(wn * 128 + r0) * 2 + 1]     = q0;
            reds[(wn * 128 + r0 + 8) * 2]     = s1;
            reds[(wn * 128 + r0 + 8) * 2 + 1] = q1;
        }
    }
    __syncthreads();

    // ---- E2: finalize LN stats ----
    if (tid < 128) {
        float s = reds[tid * 2] + reds[(128 + tid) * 2]
                + reds[(256 + tid) * 2] + reds[(384 + tid) * 2];
        float q = reds[tid * 2 + 1] + reds[(128 + tid) * 2 + 1]
                + reds[(256 + tid) * 2 + 1] + reds[(384 + tid) * 2 + 1];
        float mean = s * (1.0f / CC);
        float var  = q * (1.0f / CC) - mean * mean;
        mrs[tid] = mean;
        mrs[128 + tid] = rsqrtf(var + LN_EPS);
    }
    __syncthreads();

    // ---- E3: score dots via MMA; B = wq^T [h][k] non-trans x2 ----
    {
        float cd[4] = {0.f, 0.f, 0.f, 0.f};
        #pragma unroll
        for (int k8 = 0; k8 < 16; k8++) {
            uint32_t a[4];
            ldsm_x4(a, sbase + SM_XBF
                       + (uint32_t)(wid * 16 + (grp & 1) * 8 + jj) * PITCHX
                       + (uint32_t)(k8 * 16 + (grp >> 1) * 8) * 2);
            uint32_t bb[2];
            ldsm_x2(bb, sbase + SM_WQT + (uint32_t)(lane & 7) * PITCHX
                       + (uint32_t)(k8 * 16 + ((lane >> 3) & 1) * 8) * 2);
            mma16816(cd, a, bb);
        }
        int r = wid * 16 + (lane >> 2);
        int h0 = (lane & 3) * 2;
        int glb = tile * TILE;
        #pragma unroll
        for (int e = 0; e < 4; e++) {
            int row = r + (e >> 1) * 8;
            int h = h0 + (e & 1);
            float mean = mrs[row], rstd = mrs[128 + row];
            float sv = (rstd * (cd[e] - mean * g_sg[b * NH + h])
                        + g_bw[b * NH + h] + g_qb[b * NH + h]) * SCALE_ATT
                       * ior[((size_t)b * NH + h) * LL + glb + row];
            s_s[row * 8 + h] = sv;
        }
    }
    __syncthreads();

    // ---- E4: softmax partials (warp-parallel: warp wid owns head wid) ----
    {
        int h = wid;
        float m = -1e30f;
        #pragma unroll
        for (int i = 0; i < 4; i++)
            m = fmaxf(m, s_s[(lane + i * 32) * 8 + h]);
        #pragma unroll
        for (int o = 16; o > 0; o >>= 1) m = fmaxf(m, __shfl_xor_sync(~0u, m, o));
        if (lane == 0) mh[h] = m;
    }
    __syncthreads();
    if (tid < 128) {
        #pragma unroll
        for (int h = 0; h < NH; h++)
            s_s[tid * 8 + h] = __expf(s_s[tid * 8 + h] - mh[h]);
    }
    __syncthreads();
    {
        int h = wid;
        float D = 0.f, Q = 0.f;
        #pragma unroll
        for (int i = 0; i < 4; i++) {
            int j = lane + i * 32;
            float p = s_s[j * 8 + h];
            D += p;
            Q += p * mrs[128 + j] * mrs[j];
        }
        #pragma unroll
        for (int o = 16; o > 0; o >>= 1) {
            D += __shfl_xor_sync(~0u, D, o);
            Q += __shfl_xor_sync(~0u, Q, o);
        }
        if (lane == 0) {
            float* md = &g_md[(size_t)((b * NTILES + tile) * NH + h) * 4];
            md[0] = mh[h];
            md[1] = D;
            md[2] = Q;
        }
    }

    // ---- E5: pT bf16 [h][j] (rstd folded), zero rows 8-15 ----
    if (tid < 128) {
        float rstd = mrs[128 + tid];
        #pragma unroll
        for (int h = 0; h < NH; h++)
            *(__nv_bfloat16*)(sb + SM_PT + (uint32_t)h * PITCHB + (uint32_t)tid * 2)
                = __float2bfloat16(s_s[tid * 8 + h] * rstd);
    }
    for (int i = tid; i < 1088; i += 256)
        *(unsigned short*)(sb + SM_PT + 8 * PITCHB + (uint32_t)i * 2) = 0;
    __syncthreads();

    // ---- E6: T = pT @ x via MMA; B = xT [c][j] non-trans x4 ----
    {
        float ct[4][4];
        #pragma unroll
        for (int q = 0; q < 4; q++)
            #pragma unroll
            for (int e = 0; e < 4; e++) ct[q][e] = 0.f;
        #pragma unroll
        for (int k8 = 0; k8 < 8; k8++) {
            int j0 = k8 * 16;
            uint32_t a[4];
            ldsm_x4(a, sbase + SM_PT + (uint32_t)((grp & 1) * 8 + jj) * PITCHB
                       + (uint32_t)(j0 + (grp >> 1) * 8) * 2);
            #pragma unroll
            for (int np = 0; np < 2; np++) {
                uint32_t bb[4];
                ldsm_x4(bb, sbase + SM_XT
                           + (uint32_t)(wid * 32 + np * 16 + (grp >> 1) * 8 + jj) * PITCHB
                           + (uint32_t)(j0 + (grp & 1) * 8) * 2);
                mma16816(ct[np * 2 + 0], a, bb + 0);
                mma16816(ct[np * 2 + 1], a, bb + 2);
            }
        }
        int h = lane >> 2;
        float* gp = g_part + (size_t)((b * NTILES + tile) * NH + h) * CC;
        #pragma unroll
        for (int q = 0; q < 4; q++) {
            int c = wid * 32 + (q >> 1) * 16 + (q & 1) * 8 + (lane & 3) * 2;
            gp[c]     = ct[q][0];
            gp[c + 1] = ct[q][1];
        }
    }
}

// ---------------- K3: combine tiles + project through W_v ----------------
__global__ void k3_combine(const float* __restrict__ W_kv, const float* __restrict__ b_kv,
                           const float* __restrict__ g_ip, const float* __restrict__ be_ip) {
    int b = blockIdx.x >> 3, h = blockIdx.x & 7, tid = threadIdx.x;
    __shared__ float w_s[NTILES];
    __shared__ float tv[CC];
    __shared__ float redx[256];
    __shared__ float rsc[8], rsc2[8], rsc3[8];

    float Mt = -1e30f, Dt = 0.f, Qt = 0.f;
    if (tid < NTILES) {
        const float* md = &g_md[(size_t)((b * NTILES + tid) * NH + h) * 4];
        Mt = md[0]; Dt = md[1]; Qt = md[2];
    }

    float m = Mt;
    #pragma unroll
    for (int o = 16; o > 0; o >>= 1) m = fmaxf(m, __shfl_xor_sync(~0u, m, o));
    if ((tid & 31) == 0) rsc[tid >> 5] = m;
    __syncthreads();
    float M = rsc[0];
    #pragma unroll
    for (int i = 1; i < 8; i++) M = fmaxf(M, rsc[i]);

    float sc = __expf(Mt - M);
    if (tid < NTILES) w_s[tid] = sc;
    float dp = sc * Dt, qp = sc * Qt;
    __syncthreads();
    #pragma unroll
    for (int o = 16; o > 0; o >>= 1) {
        dp += __shfl_xor_sync(~0u, dp, o);
        qp += __shfl_xor_sync(~0u, qp, o);
    }
    if ((tid & 31) == 0) { rsc2[tid >> 5] = dp; rsc3[tid >> 5] = qp; }
    __syncthreads();
    float D = 0.f, Q = 0.f;
    #pragma unroll
    for (int i = 0; i < 8; i++) { D += rsc2[i]; Q += rsc3[i]; }

    float acc = 0.f;
    const float* base = g_part + (size_t)(b * NTILES) * NH * CC + (size_t)h * CC + tid;
    for (int t2 = 0; t2 < NTILES; t2++) acc += w_s[t2] * base[(size_t)t2 * NH * CC];
    tv[tid] = g_ip[tid] * (acc - Q) / D + be_ip[tid];
    __syncthreads();

    int d = tid & 31, g = tid >> 5;
    float a = 0.f;
    for (int k = g * 32; k < g * 32 + 32; k++)
        a += tv[k] * W_kv[(size_t)k * (2 * CC) + CC + h * HD + d];
    redx[g * 32 + d] = a;
    __syncthreads();
    if (tid < 32) {
        float s = 0.f;
        #pragma unroll
        for (int gg = 0; gg < 8; gg++) s += redx[gg * 32 + tid];
        g_attn[b * CC + h * HD + tid] = s + b_kv[CC + h * HD + tid];
    }
}

// ---------------- K4a/b/c ----------------
__global__ void k4a_ln(const float* __restrict__ query,
                       const float* __restrict__ g_f, const float* __restrict__ be_f) {
    int b = blockIdx.x, tid = threadIdx.x;
    __shared__ float rs[8], rs2[8];
    float x = g_attn[b * CC + tid] + query[b * CC + tid];
    g_x[b * CC + tid] = x;
    float s = x, s2 = x * x;
    #pragma unroll
    for (int o = 16; o > 0; o >>= 1) {
        s  += __shfl_xor_sync(~0u, s,  o);
        s2 += __shfl_xor_sync(~0u, s2, o);
    }
    if ((tid & 31) == 0) { rs[tid >> 5] = s; rs2[tid >> 5] = s2; }
    __syncthreads();
    float tot = 0.f, tot2 = 0.f;
    #pragma unroll
    for (int i = 0; i < 8; i++) { tot += rs[i]; tot2 += rs2[i]; }
    float mean = tot * (1.0f / CC);
    float var  = tot2 * (1.0f / CC) - mean * mean;
    float rstd = rsqrtf(var + LN_EPS);
    g_hn[b * CC + tid] = (x - mean) * rstd * g_f[tid] + be_f[tid];
}

__global__ void k4b_ffn1(const float* __restrict__ W1, const float* __restrict__ b1) {
    int b = blockIdx.y, tid = threadIdx.x;
    int f = blockIdx.x * 64 + (tid & 63);
    int ks = tid >> 6;
    __shared__ float red[256];
    const float* hn = &g_hn[b * CC];
    float acc = 0.f;
    for (int k = ks * 64; k < ks * 64 + 64; k++)
        acc += hn[k] * W1[(size_t)k * 512 + f];
    red[tid] = acc;
    __syncthreads();
    if (tid < 64) {
        float a = red[tid] + red[64 + tid] + red[128 + tid] + red[192 + tid] + b1[f];
        g_h1[b * 512 + f] = 0.5f * a * (1.0f + erff(a * 0.70710678118654752f));
    }
}

__global__ void k4c_ffn2(const float* __restrict__ W2, const float* __restrict__ b2,
                         float* __restrict__ out) {
    int b = blockIdx.y, tid = threadIdx.x;
    int c = blockIdx.x * 64 + (tid & 63);
    int ks = tid >> 6;
    __shared__ float red[256];
    const float* h1 = &g_h1[b * 512];
    float acc = 0.f;
    for (int k = ks * 128; k < ks * 128 + 128; k++)
        acc += h1[k] * W2[(size_t)k * CC + c];
    red[tid] = acc;
    __syncthreads();
    if (tid < 64) {
        float a = red[tid] + red[64 + tid] + red[128 + tid] + red[192 + tid];
        out[b * CC + c] = g_x[b * CC + c] + a + b2[c];
    }
}

// ---------------- launch ----------------
extern "C" void kernel_launch(void* const* d_in, const int* in_sizes, int n_in,
                              void* d_out, int out_size) {
    const float* query = (const float*)d_in[0];
    const float* mem   = (const float*)d_in[1];
    const float* ior   = (const float*)d_in[2];
    const float* W_ip  = (const float*)d_in[3];
    const float* b_ip  = (const float*)d_in[4];
    const float* g_ipp = (const float*)d_in[5];
    const float* be_ip = (const float*)d_in[6];
    const float* W_q   = (const float*)d_in[7];
    const float* b_q   = (const float*)d_in[8];
    const float* W_kv  = (const float*)d_in[9];
    const float* b_kv  = (const float*)d_in[10];
    const float* g_q   = (const float*)d_in[11];
    const float* be_q  = (const float*)d_in[12];
    const float* g_f   = (const float*)d_in[13];
    const float* be_f  = (const float*)d_in[14];
    const float* W1    = (const float*)d_in[15];
    const float* b1    = (const float*)d_in[16];
    const float* W2    = (const float*)d_in[17];
    const float* b2    = (const float*)d_in[18];
    float* out = (float*)d_out;

    cudaFuncSetAttribute(k2_main, cudaFuncAttributeMaxDynamicSharedMemorySize,
                         (int)SM_TOTAL);

    k0_wprep<<<256, 256>>>(W_ip);
    k1_qprep<<<BB, 256>>>(query, g_q, be_q, W_q, b_q, W_kv, b_kv, g_ipp, be_ip);
    k2_main<<<dim3(NTILES, BB), 256, SM_TOTAL>>>(mem, ior, b_ip);
    k3_combine<<<BB * NH, 256>>>(W_kv, b_kv, g_ipp, be_ip);
    k4a_ln<<<BB, 256>>>(query, g_f, be_f);
    k4b_ffn1<<<dim3(8, BB), 256>>>(W1, b1);
    k4c_ffn2<<<dim3(4, BB), 256>>>(W2, b2, out);
}

// round 11
// speedup vs baseline: 9.2225x; 1.1414x over previous
#include <cuda_runtime.h>
#include <cuda_bf16.h>
#include <math.h>
#include <stdint.h>

#define BB 16
#define LL 16384
#define CC 256
#define NH 8
#define HD 32
#define TILE 64
#define NTILES (LL / TILE)          // 256
#define SCALE_ATT 0.17677669529663687f
#define LN_EPS 1e-5f

#define PITCHH 272u    // bytes per 128-col bf16 row (A/B half tiles)
#define PITCHXB 528u   // bytes per 256-col bf16 row (XBF, WQT)
#define PITCHT 144u    // bytes per 64-col bf16 row (+pad) (XT, PT)

// ---------------- device scratch ----------------
__device__ float g_wq[BB * CC * NH];
__device__ float g_qb[BB * NH];
__device__ float g_sg[BB * NH];
__device__ float g_bw[BB * NH];
__device__ __nv_bfloat16 g_part[BB * NTILES * NH * CC];  // bf16, L2-resident (32MB)
__device__ float g_md[BB * NTILES * NH * 4];
__device__ float g_attn[BB * CC];
__device__ __nv_bfloat16 g_bflat[CC * CC];        // W_ip^T bf16 [n][k]
__device__ float g_x[BB * CC];
__device__ float g_hn[BB * CC];
__device__ float g_h1[BB * 512];

// ---------------- helpers ----------------
__device__ __forceinline__ uint32_t smem_u32(const void* p) {
    uint32_t a;
    asm("{ .reg .u64 t; cvta.to.shared.u64 t, %1; cvt.u32.u64 %0, t; }" : "=r"(a) : "l"(p));
    return a;
}
__device__ __forceinline__ void ldsm_x4(uint32_t* r, uint32_t a) {
    asm volatile("ldmatrix.sync.aligned.m8n8.x4.shared.b16 {%0,%1,%2,%3}, [%4];"
                 : "=r"(r[0]), "=r"(r[1]), "=r"(r[2]), "=r"(r[3]) : "r"(a));
}
__device__ __forceinline__ void ldsm_x2(uint32_t* r, uint32_t a) {
    asm volatile("ldmatrix.sync.aligned.m8n8.x2.shared.b16 {%0,%1}, [%2];"
                 : "=r"(r[0]), "=r"(r[1]) : "r"(a));
}
__device__ __forceinline__ void mma16816(float* c, const uint32_t* a, const uint32_t* b) {
    asm volatile("mma.sync.aligned.m16n8k16.row.col.f32.bf16.bf16.f32 "
                 "{%0,%1,%2,%3}, {%4,%5,%6,%7}, {%8,%9}, {%0,%1,%2,%3};"
                 : "+f"(c[0]), "+f"(c[1]), "+f"(c[2]), "+f"(c[3])
                 : "r"(a[0]), "r"(a[1]), "r"(a[2]), "r"(a[3]), "r"(b[0]), "r"(b[1]));
}
// packed convert: low half = lo, high half = hi (PTX: first source -> high)
__device__ __forceinline__ uint32_t cvt2(float lo, float hi) {
    uint32_t r;
    asm("cvt.rn.bf16x2.f32 %0, %1, %2;" : "=r"(r) : "f"(hi), "f"(lo));
    return r;
}
__device__ __forceinline__ void cp_async16(uint32_t dst, const void* src) {
    asm volatile("cp.async.cg.shared.global [%0], [%1], 16;" :: "r"(dst), "l"(src));
}
__device__ __forceinline__ void cp_commit() {
    asm volatile("cp.async.commit_group;" ::: "memory");
}
__device__ __forceinline__ void cp_wait0() {
    asm volatile("cp.async.wait_group 0;" ::: "memory");
}

// ---------------- K0: W_ip^T -> bf16 [n][k] ----------------
__global__ void k0_wprep(const float* __restrict__ W_ip) {
    int k = blockIdx.x;
    int n = threadIdx.x;
    g_bflat[(size_t)n * CC + k] = __float2bfloat16(W_ip[(size_t)k * CC + n]);
}

// ---------------- K1: q-path prep ----------------
__global__ void k1_qprep(const float* __restrict__ query,
                         const float* __restrict__ g_q, const float* __restrict__ be_q,
                         const float* __restrict__ W_q, const float* __restrict__ b_q,
                         const float* __restrict__ W_kv, const float* __restrict__ b_kv,
                         const float* __restrict__ g_ip, const float* __restrict__ be_ip) {
    int b = blockIdx.x;
    int tid = threadIdx.x;
    __shared__ float qn[CC], qp[CC], wraw[CC * NH], rs[8], rs2[8];

    float v = query[b * CC + tid];
    float s = v, s2 = v * v;
    #pragma unroll
    for (int o = 16; o > 0; o >>= 1) {
        s  += __shfl_xor_sync(~0u, s,  o);
        s2 += __shfl_xor_sync(~0u, s2, o);
    }
    if ((tid & 31) == 0) { rs[tid >> 5] = s; rs2[tid >> 5] = s2; }
    __syncthreads();
    float tot = 0.f, tot2 = 0.f;
    #pragma unroll
    for (int i = 0; i < 8; i++) { tot += rs[i]; tot2 += rs2[i]; }
    float mean = tot * (1.0f / CC);
    float var  = tot2 * (1.0f / CC) - mean * mean;
    float rstd = rsqrtf(var + LN_EPS);
    qn[tid] = (v - mean) * rstd * g_q[tid] + be_q[tid];
    __syncthreads();

    float acc = b_q[tid];
    for (int k = 0; k < CC; k++) acc += qn[k] * W_q[k * CC + tid];
    qp[tid] = acc;
    __syncthreads();

    int k = tid;
    float gk = g_ip[k];
    #pragma unroll
    for (int h = 0; h < NH; h++) {
        float a = 0.f;
        const float* wrow = W_kv + (size_t)k * (2 * CC) + h * HD;
        const float* qh = qp + h * HD;
        #pragma unroll
        for (int d = 0; d < HD; d++) a += qh[d] * wrow[d];
        wraw[k * NH + h] = a;
        g_wq[(b * CC + k) * NH + h] = gk * a;
    }
    if (tid < NH) {
        float a = 0.f;
        const float* qh = qp + tid * HD;
        const float* bk = b_kv + tid * HD;
        #pragma unroll
        for (int d = 0; d < HD; d++) a += qh[d] * bk[d];
        g_qb[b * NH + tid] = a;
    }
    __syncthreads();
    if (tid < NH) {
        float sg = 0.f, bw = 0.f;
        for (int kk = 0; kk < CC; kk++) {
            float r = wraw[kk * NH + tid];
            sg += g_ip[kk] * r;
            bw += be_ip[kk] * r;
        }
        g_sg[b * NH + tid] = sg;
        g_bw[b * NH + tid] = bw;
    }
}

// ---------------- K2 smem layout (bytes), TILE=64, K-half staging ----------------
#define SM_A     0u          // 64*272 = 17408
#define SM_B     17408u      // 256*272 = 69632 -> 87040
#define SM_BIAS  87040u      // 1024
#define SM_WQT   88064u      // 8*528 = 4224 -> 92288
#define SM_TOTAL 92288u
// overlays (valid after GEMM; A+B dead, all < 87040):
#define SM_XBF   0u          // 64*528 = 33792
#define SM_XT    33792u      // 256*144 = 36864 -> 70656
#define SM_REDS  70656u      // 4*64*2*4 = 2048
#define SM_SS    72704u      // 64*8*4 = 2048
#define SM_MRS   74752u      // 128*4 = 512
#define SM_MH    75264u      // 64
#define SM_PT    75328u      // 16*144 = 2304 -> 77632

extern __shared__ char k2smem[];

__global__ __launch_bounds__(256, 2)
void k2_main(const float* __restrict__ mem, const float* __restrict__ ior,
             const float* __restrict__ b_ip) {
    int b = blockIdx.y, tile = blockIdx.x, tid = threadIdx.x;
    int wid = tid >> 5, lane = tid & 31;
    char* sb = k2smem;
    uint32_t sbase = smem_u32(sb);
    float* bias = (float*)(sb + SM_BIAS);
    float* s_s  = (float*)(sb + SM_SS);
    float* mrs  = (float*)(sb + SM_MRS);
    float* mh   = (float*)(sb + SM_MH);
    float* reds = (float*)(sb + SM_REDS);

    // constants: bias + wq^T [h][k] bf16
    bias[tid] = b_ip[tid];
    {
        const float* wp = &g_wq[(size_t)(b * CC + tid) * NH];
        #pragma unroll
        for (int h = 0; h < NH; h++)
            *(__nv_bfloat16*)(sb + SM_WQT + (uint32_t)h * PITCHXB + (uint32_t)tid * 2)
                = __float2bfloat16(wp[h]);
    }

    int wm = wid >> 2, wn = wid & 3;
    int m_base = wm * 32, n_base = wn * 64;
    int grp = lane >> 3, jj = lane & 7;

    float acc[2][8][4];
    #pragma unroll
    for (int mt = 0; mt < 2; mt++)
        #pragma unroll
        for (int nt = 0; nt < 8; nt++)
            #pragma unroll
            for (int e = 0; e < 4; e++) acc[mt][nt][e] = 0.f;

    const float* memp = mem + ((size_t)b * LL + (size_t)tile * TILE) * CC;

    for (int h = 0; h < 2; h++) {
        __syncthreads();
        // B half via cp.async: g_bflat [n][k], half-k slice, re-pitch 256B->272B
        #pragma unroll
        for (int i = 0; i < 16; i++) {
            int u = tid + i * 256;                // 4096 = 256 rows * 16 units
            int row = u >> 4, c16 = u & 15;
            cp_async16(sbase + SM_B + (uint32_t)row * PITCHH + (uint32_t)c16 * 16,
                       (const char*)g_bflat + (size_t)row * 512 + h * 256 + c16 * 16);
        }
        cp_commit();
        // A half: fp32 -> bf16
        #pragma unroll
        for (int i = 0; i < 8; i++) {
            int f4 = tid + i * 256;               // 2048 = 64 rows * 32 f4
            int row = f4 >> 5, c4 = f4 & 31;
            float4 v = ((const float4*)(memp + (size_t)row * CC + h * 128))[c4];
            uint2 u;
            u.x = cvt2(v.x, v.y); u.y = cvt2(v.z, v.w);
            *(uint2*)(sb + SM_A + (uint32_t)row * PITCHH + (uint32_t)c4 * 8) = u;
        }
        cp_wait0();
        __syncthreads();

        // single-pass bf16 MMA over this K-half
        #pragma unroll
        for (int k8 = 0; k8 < 8; k8++) {
            int k0 = k8 * 16;
            uint32_t arow = (uint32_t)(m_base + (grp & 1) * 8 + jj) * PITCHH
                          + (uint32_t)(k0 + (grp >> 1) * 8) * 2;
            uint32_t a[2][4];
            #pragma unroll
            for (int mt = 0; mt < 2; mt++)
                ldsm_x4(a[mt], sbase + SM_A + arow + (uint32_t)mt * 16 * PITCHH);
            uint32_t brow = (uint32_t)(n_base + (grp >> 1) * 8 + jj) * PITCHH
                          + (uint32_t)(k0 + (grp & 1) * 8) * 2;
            #pragma unroll
            for (int np = 0; np < 4; np++) {
                uint32_t bb[4];
                ldsm_x4(bb, sbase + SM_B + brow + (uint32_t)np * 16 * PITCHH);
                #pragma unroll
                for (int mt = 0; mt < 2; mt++) {
                    mma16816(acc[mt][np * 2 + 0], a[mt], bb + 0);
                    mma16816(acc[mt][np * 2 + 1], a[mt], bb + 2);
                }
            }
        }
    }
    __syncthreads();    // tiles dead; overlays live

    // E1: bias+relu -> XBF [j][c] + XT [c][j], LN partials
    #pragma unroll
    for (int mt = 0; mt < 2; mt++) {
        int r0 = m_base + mt * 16 + (lane >> 2);
        float s0 = 0.f, q0 = 0.f, s1 = 0.f, q1 = 0.f;
        #pragma unroll
        for (int nt = 0; nt < 8; nt++) {
            int n = n_base + nt * 8 + (lane & 3) * 2;
            float b0 = bias[n], b1 = bias[n + 1];
            float x00 = fmaxf(acc[mt][nt][0] + b0, 0.f);
            float x01 = fmaxf(acc[mt][nt][1] + b1, 0.f);
            float x10 = fmaxf(acc[mt][nt][2] + b0, 0.f);
            float x11 = fmaxf(acc[mt][nt][3] + b1, 0.f);
            s0 += x00 + x01; q0 += x00 * x00 + x01 * x01;
            s1 += x10 + x11; q1 += x10 * x10 + x11 * x11;
            *(uint32_t*)(sb + SM_XBF + (uint32_t)r0 * PITCHXB + (uint32_t)n * 2)
                = cvt2(x00, x01);
            *(uint32_t*)(sb + SM_XBF + (uint32_t)(r0 + 8) * PITCHXB + (uint32_t)n * 2)
                = cvt2(x10, x11);
            *(__nv_bfloat16*)(sb + SM_XT + (uint32_t)n * PITCHT + (uint32_t)r0 * 2)
                = __float2bfloat16(x00);
            *(__nv_bfloat16*)(sb + SM_XT + (uint32_t)(n + 1) * PITCHT + (uint32_t)r0 * 2)
                = __float2bfloat16(x01);
            *(__nv_bfloat16*)(sb + SM_XT + (uint32_t)n * PITCHT + (uint32_t)(r0 + 8) * 2)
                = __float2bfloat16(x10);
            *(__nv_bfloat16*)(sb + SM_XT + (uint32_t)(n + 1) * PITCHT + (uint32_t)(r0 + 8) * 2)
                = __float2bfloat16(x11);
        }
        #pragma unroll
        for (int o = 1; o <= 2; o <<= 1) {
            s0 += __shfl_xor_sync(~0u, s0, o); q0 += __shfl_xor_sync(~0u, q0, o);
            s1 += __shfl_xor_sync(~0u, s1, o); q1 += __shfl_xor_sync(~0u, q1, o);
        }
        if ((lane & 3) == 0) {
            reds[(wn * 64 + r0) * 2]         = s0;
            reds[(wn * 64 + r0) * 2 + 1]     = q0;
            reds[(wn * 64 + r0 + 8) * 2]     = s1;
            reds[(wn * 64 + r0 + 8) * 2 + 1] = q1;
        }
    }
    __syncthreads();

    // E2: finalize LN stats (64 rows)
    if (tid < 64) {
        float s = reds[tid * 2] + reds[(64 + tid) * 2]
                + reds[(128 + tid) * 2] + reds[(192 + tid) * 2];
        float q = reds[tid * 2 + 1] + reds[(64 + tid) * 2 + 1]
                + reds[(128 + tid) * 2 + 1] + reds[(192 + tid) * 2 + 1];
        float mean = s * (1.0f / CC);
        float var  = q * (1.0f / CC) - mean * mean;
        mrs[tid] = mean;
        mrs[64 + tid] = rsqrtf(var + LN_EPS);
    }
    __syncthreads();

    // E3: score dots via MMA (warps 0-3: 16 rows each, full K=256)
    if (wid < 4) {
        float cd[4] = {0.f, 0.f, 0.f, 0.f};
        #pragma unroll
        for (int k8 = 0; k8 < 16; k8++) {
            uint32_t a[4];
            ldsm_x4(a, sbase + SM_XBF
                       + (uint32_t)(wid * 16 + (grp & 1) * 8 + jj) * PITCHXB
                       + (uint32_t)(k8 * 16 + (grp >> 1) * 8) * 2);
            uint32_t bb[2];
            ldsm_x2(bb, sbase + SM_WQT + (uint32_t)(lane & 7) * PITCHXB
                       + (uint32_t)(k8 * 16 + ((lane >> 3) & 1) * 8) * 2);
            mma16816(cd, a, bb);
        }
        int r = wid * 16 + (lane >> 2);
        int h0 = (lane & 3) * 2;
        int glb = tile * TILE;
        #pragma unroll
        for (int e = 0; e < 4; e++) {
            int row = r + (e >> 1) * 8;
            int h = h0 + (e & 1);
            float mean = mrs[row], rstd = mrs[64 + row];
            float sv = (rstd * (cd[e] - mean * g_sg[b * NH + h])
                        + g_bw[b * NH + h] + g_qb[b * NH + h]) * SCALE_ATT
                       * ior[((size_t)b * NH + h) * LL + glb + row];
            s_s[row * 8 + h] = sv;
        }
    }
    __syncthreads();

    // E4: per-head max (warp wid owns head wid, 64 j)
    {
        int h = wid;
        float m = fmaxf(s_s[lane * 8 + h], s_s[(lane + 32) * 8 + h]);
        #pragma unroll
        for (int o = 16; o > 0; o >>= 1) m = fmaxf(m, __shfl_xor_sync(~0u, m, o));
        if (lane == 0) mh[h] = m;
    }
    __syncthreads();
    // exp (512 values, 2 per thread)
    #pragma unroll
    for (int i = 0; i < 2; i++) {
        int idx = tid + i * 256;
        s_s[idx] = __expf(s_s[idx] - mh[idx & 7]);
    }
    __syncthreads();
    // D, Q per head + pT bf16 [h][j] (rstd folded)
    {
        int h = wid;
        float D = 0.f, Q = 0.f;
        #pragma unroll
        for (int i = 0; i < 2; i++) {
            int j = lane + i * 32;
            float p = s_s[j * 8 + h];
            D += p;
            Q += p * mrs[64 + j] * mrs[j];
        }
        #pragma unroll
        for (int o = 16; o > 0; o >>= 1) {
            D += __shfl_xor_sync(~0u, D, o);
            Q += __shfl_xor_sync(~0u, Q, o);
        }
        if (lane == 0) {
            float* md = &g_md[(size_t)((b * NTILES + tile) * NH + h) * 4];
            md[0] = mh[h];
            md[1] = D;
            md[2] = Q;
        }
    }
    if (tid < 64) {
        float rstd = mrs[64 + tid];
        #pragma unroll
        for (int h = 0; h < NH; h++)
            *(__nv_bfloat16*)(sb + SM_PT + (uint32_t)h * PITCHT + (uint32_t)tid * 2)
                = __float2bfloat16(s_s[tid * 8 + h] * rstd);
    }
    for (int i = tid; i < 576; i += 256)       // zero pad rows 8..15
        *(unsigned short*)(sb + SM_PT + 8 * PITCHT + (uint32_t)i * 2) = 0;
    __syncthreads();

    // E6: T = pT @ x via MMA; B = XT [c][j] non-trans x4; warp owns 32 c-cols
    {
        float ct[4][4];
        #pragma unroll
        for (int q = 0; q < 4; q++)
            #pragma unroll
            for (int e = 0; e < 4; e++) ct[q][e] = 0.f;
        #pragma unroll
        for (int k8 = 0; k8 < 4; k8++) {
            int j0 = k8 * 16;
            uint32_t a[4];
            ldsm_x4(a, sbase + SM_PT + (uint32_t)((grp & 1) * 8 + jj) * PITCHT
                       + (uint32_t)(j0 + (grp >> 1) * 8) * 2);
            #pragma unroll
            for (int np = 0; np < 2; np++) {
                uint32_t bb[4];
                ldsm_x4(bb, sbase + SM_XT
                           + (uint32_t)(wid * 32 + np * 16 + (grp >> 1) * 8 + jj) * PITCHT
                           + (uint32_t)(j0 + (grp & 1) * 8) * 2);
                mma16816(ct[np * 2 + 0], a, bb + 0);
                mma16816(ct[np * 2 + 1], a, bb + 2);
            }
        }
        int h = lane >> 2;
        __nv_bfloat16* gp = g_part + (size_t)((b * NTILES + tile) * NH + h) * CC;
        #pragma unroll
        for (int q = 0; q < 4; q++) {
            int c = wid * 32 + (q >> 1) * 16 + (q & 1) * 8 + (lane & 3) * 2;
            *(uint32_t*)&gp[c] = cvt2(ct[q][0], ct[q][1]);
        }
    }
}

// ---------------- K3: combine tiles + project through W_v ----------------
__global__ void k3_combine(const float* __restrict__ W_kv, const float* __restrict__ b_kv,
                           const float* __restrict__ g_ip, const float* __restrict__ be_ip) {
    int b = blockIdx.x >> 3, h = blockIdx.x & 7, tid = threadIdx.x;
    __shared__ float w_s[NTILES];
    __shared__ float tv[CC];
    __shared__ float redx[256];
    __shared__ float rsc[8], rsc2[8], rsc3[8];

    const float* md = &g_md[(size_t)((b * NTILES + tid) * NH + h) * 4];
    float Mt = md[0], Dt = md[1], Qt = md[2];

    float m = Mt;
    #pragma unroll
    for (int o = 16; o > 0; o >>= 1) m = fmaxf(m, __shfl_xor_sync(~0u, m, o));
    if ((tid & 31) == 0) rsc[tid >> 5] = m;
    __syncthreads();
    float M = rsc[0];
    #pragma unroll
    for (int i = 1; i < 8; i++) M = fmaxf(M, rsc[i]);

    float sc = __expf(Mt - M);
    w_s[tid] = sc;
    float dp = sc * Dt, qp = sc * Qt;
    __syncthreads();
    #pragma unroll
    for (int o = 16; o > 0; o >>= 1) {
        dp += __shfl_xor_sync(~0u, dp, o);
        qp += __shfl_xor_sync(~0u, qp, o);
    }
    if ((tid & 31) == 0) { rsc2[tid >> 5] = dp; rsc3[tid >> 5] = qp; }
    __syncthreads();
    float D = 0.f, Q = 0.f;
    #pragma unroll
    for (int i = 0; i < 8; i++) { D += rsc2[i]; Q += rsc3[i]; }

    float acc = 0.f;
    const __nv_bfloat16* base = g_part + (size_t)(b * NTILES) * NH * CC
                              + (size_t)h * CC + tid;
    for (int t2 = 0; t2 < NTILES; t2++)
        acc += w_s[t2] * __bfloat162float(base[(size_t)t2 * NH * CC]);
    tv[tid] = g_ip[tid] * (acc - Q) / D + be_ip[tid];
    __syncthreads();

    int d = tid & 31, g = tid >> 5;
    float a = 0.f;
    for (int k = g * 32; k < g * 32 + 32; k++)
        a += tv[k] * W_kv[(size_t)k * (2 * CC) + CC + h * HD + d];
    redx[g * 32 + d] = a;
    __syncthreads();
    if (tid < 32) {
        float s = 0.f;
        #pragma unroll
        for (int gg = 0; gg < 8; gg++) s += redx[gg * 32 + tid];
        g_attn[b * CC + h * HD + tid] = s + b_kv[CC + h * HD + tid];
    }
}

// ---------------- K4a/b/c ----------------
__global__ void k4a_ln(const float* __restrict__ query,
                       const float* __restrict__ g_f, const float* __restrict__ be_f) {
    int b = blockIdx.x, tid = threadIdx.x;
    __shared__ float rs[8], rs2[8];
    float x = g_attn[b * CC + tid] + query[b * CC + tid];
    g_x[b * CC + tid] = x;
    float s = x, s2 = x * x;
    #pragma unroll
    for (int o = 16; o > 0; o >>= 1) {
        s  += __shfl_xor_sync(~0u, s,  o);
        s2 += __shfl_xor_sync(~0u, s2, o);
    }
    if ((tid & 31) == 0) { rs[tid >> 5] = s; rs2[tid >> 5] = s2; }
    __syncthreads();
    float tot = 0.f, tot2 = 0.f;
    #pragma unroll
    for (int i = 0; i < 8; i++) { tot += rs[i]; tot2 += rs2[i]; }
    float mean = tot * (1.0f / CC);
    float var  = tot2 * (1.0f / CC) - mean * mean;
    float rstd = rsqrtf(var + LN_EPS);
    g_hn[b * CC + tid] = (x - mean) * rstd * g_f[tid] + be_f[tid];
}

__global__ void k4b_ffn1(const float* __restrict__ W1, const float* __restrict__ b1) {
    int b = blockIdx.y, tid = threadIdx.x;
    int f = blockIdx.x * 64 + (tid & 63);
    int ks = tid >> 6;
    __shared__ float red[256];
    const float* hn = &g_hn[b * CC];
    float acc = 0.f;
    for (int k = ks * 64; k < ks * 64 + 64; k++)
        acc += hn[k] * W1[(size_t)k * 512 + f];
    red[tid] = acc;
    __syncthreads();
    if (tid < 64) {
        float a = red[tid] + red[64 + tid] + red[128 + tid] + red[192 + tid] + b1[f];
        g_h1[b * 512 + f] = 0.5f * a * (1.0f + erff(a * 0.70710678118654752f));
    }
}

__global__ void k4c_ffn2(const float* __restrict__ W2, const float* __restrict__ b2,
                         float* __restrict__ out) {
    int b = blockIdx.y, tid = threadIdx.x;
    int c = blockIdx.x * 64 + (tid & 63);
    int ks = tid >> 6;
    __shared__ float red[256];
    const float* h1 = &g_h1[b * 512];
    float acc = 0.f;
    for (int k = ks * 128; k < ks * 128 + 128; k++)
        acc += h1[k] * W2[(size_t)k * CC + c];
    red[tid] = acc;
    __syncthreads();
    if (tid < 64) {
        float a = red[tid] + red[64 + tid] + red[128 + tid] + red[192 + tid];
        out[b * CC + c] = g_x[b * CC + c] + a + b2[c];
    }
}

// ---------------- launch ----------------
extern "C" void kernel_launch(void* const* d_in, const int* in_sizes, int n_in,
                              void* d_out, int out_size) {
    const float* query = (const float*)d_in[0];
    const float* mem   = (const float*)d_in[1];
    const float* ior   = (const float*)d_in[2];
    const float* W_ip  = (const float*)d_in[3];
    const float* b_ip  = (const float*)d_in[4];
    const float* g_ipp = (const float*)d_in[5];
    const float* be_ip = (const float*)d_in[6];
    const float* W_q   = (const float*)d_in[7];
    const float* b_q   = (const float*)d_in[8];
    const float* W_kv  = (const float*)d_in[9];
    const float* b_kv  = (const float*)d_in[10];
    const float* g_q   = (const float*)d_in[11];
    const float* be_q  = (const float*)d_in[12];
    const float* g_f   = (const float*)d_in[13];
    const float* be_f  = (const float*)d_in[14];
    const float* W1    = (const float*)d_in[15];
    const float* b1    = (const float*)d_in[16];
    const float* W2    = (const float*)d_in[17];
    const float* b2    = (const float*)d_in[18];
    float* out = (float*)d_out;

    cudaFuncSetAttribute(k2_main, cudaFuncAttributeMaxDynamicSharedMemorySize,
                         (int)SM_TOTAL);

    k0_wprep<<<256, 256>>>(W_ip);
    k1_qprep<<<BB, 256>>>(query, g_q, be_q, W_q, b_q, W_kv, b_kv, g_ipp, be_ip);
    k2_main<<<dim3(NTILES, BB), 256, SM_TOTAL>>>(mem, ior, b_ip);
    k3_combine<<<BB * NH, 256>>>(W_kv, b_kv, g_ipp, be_ip);
    k4a_ln<<<BB, 256>>>(query, g_f, be_f);
    k4b_ffn1<<<dim3(8, BB), 256>>>(W1, b1);
    k4c_ffn2<<<dim3(4, BB), 256>>>(W2, b2, out);
}